// round 1
// baseline (speedup 1.0000x reference)
#include <cuda_runtime.h>
#include <math.h>

#define BATCH 16
#define H 209
#define W 133
#define CI 64
#define CO 128
#define OH 201
#define OW 129
#define NTAP 19
#define OUT_ELEMS (BATCH*OH*OW*CO)   // 53,102,592
#define AS_PITCH 81                  // 81 % 32 = 17 (odd) -> conflict-free transposed stores

// hex_indices(2) order (t matches sparse_weights layout):
// (4,2),(3,3),(5,3),(6,2),(5,1),(3,1),(2,2),(1,3),(2,4),(4,4),(6,4),(7,3),(8,2),(7,1),(6,0),(4,0),(2,0),(1,1),(0,2)
__constant__ int c_dh[NTAP] = {4,3,5,6,5,3,2,1,2,4,6,7,8,7,6,4,2,1,0};
__constant__ int c_dw[NTAP] = {2,3,3,2,1,1,2,3,4,4,4,3,2,1,0,0,0,1,2};

// transposed weights: wT[t][ci][co]
__device__ float g_wT[NTAP*CI*CO];

__global__ void prep_kernel(const float* __restrict__ sw) {
    int i = blockIdx.x * blockDim.x + threadIdx.x;
    if (i < NTAP*CI*CO) {
        int co = i % CO;
        int ci = (i / CO) % CI;
        int t  = i / (CO*CI);
        g_wT[i] = sw[(ci*CO + co)*NTAP + t];
    }
}

__global__ void zero_kernel(float4* __restrict__ out, int n4) {
    int i = blockIdx.x * blockDim.x + threadIdx.x;
    int stride = gridDim.x * blockDim.x;
    float4 z = make_float4(0.f, 0.f, 0.f, 0.f);
    for (; i < n4; i += stride) out[i] = z;
}

// ---- packed f32x2 helpers (FFMA2 path: 2x fp32 FMA throughput vs 3-reg FFMA) ----
__device__ __forceinline__ unsigned long long ffma2(unsigned long long a,
                                                    unsigned long long b,
                                                    unsigned long long c) {
    unsigned long long d;
    asm("fma.rn.f32x2 %0, %1, %2, %3;" : "=l"(d) : "l"(a), "l"(b), "l"(c));
    return d;
}
__device__ __forceinline__ unsigned long long pack_dup(float v) {
    unsigned long long r;
    unsigned int u = __float_as_uint(v);
    asm("mov.b64 %0, {%1, %2};" : "=l"(r) : "r"(u), "r"(u));
    return r;
}
__device__ __forceinline__ float2 unpack2(unsigned long long v) {
    unsigned int lo, hi;
    asm("mov.b64 {%0, %1}, %2;" : "=r"(lo), "=r"(hi) : "l"(v));
    return make_float2(__uint_as_float(lo), __uint_as_float(hi));
}

// Block: one (b, oh, co-half). Computes compacted columns owc (ow = 2*owc + (oh&1)),
// padded to 80 slots. 128 threads: tx in [0,8) -> 8 co each; ty in [0,16) -> 5 owc
// (stride 16) each. K-loop over 19 taps x 64 ci; per tap stage x-row tile (As) and
// weight tile (Bs) in smem.
__global__ __launch_bounds__(128, 4)
void conv_kernel(const float* __restrict__ x,
                 const float* __restrict__ off,
                 float* __restrict__ out) {
    __shared__ float As[CI * AS_PITCH];  // [ci][owc 0..79]
    __shared__ float Bs[CI * 64];        // [ci][co_local 0..63]

    const int oh  = blockIdx.x;
    const int b   = blockIdx.y;
    const int cb  = blockIdx.z * 64;
    const int tid = threadIdx.x;
    const int tx  = tid & 7;
    const int ty  = tid >> 3;
    const int p   = oh & 1;
    const int validw = 65 - p;           // even rows: 65 cols; odd rows: 64

    unsigned long long acc[5][4];
    #pragma unroll
    for (int i = 0; i < 5; ++i)
        #pragma unroll
        for (int j = 0; j < 4; ++j) acc[i][j] = 0ULL;

    for (int t = 0; t < NTAP; ++t) {
        const int hrow  = oh + c_dh[t];      // always < 209
        const int wbase = p + c_dw[t];       // w_in = 2*owc + wbase (<= 132 for valid owc)
        const float* xr = x + ((b*H + hrow)*W + wbase) * CI;

        // stage As[ci][owc]; coalesced gmem reads over ci, conflict-free smem stores
        #pragma unroll
        for (int e = tid; e < 80*CI; e += 128) {
            int owc = e >> 6;
            int ci  = e & 63;
            As[ci*AS_PITCH + owc] = (owc < validw) ? xr[owc*2*CI + ci] : 0.f;
        }
        // stage Bs[ci][0..63] from wT (float4)
        const float4* wsrc = (const float4*)(g_wT + t*CI*CO + cb);
        float4* bsd = (float4*)Bs;
        #pragma unroll
        for (int e = tid; e < CI*16; e += 128) {
            bsd[e] = wsrc[(e >> 4)*32 + (e & 15)];
        }
        __syncthreads();

        const float* asp = As + ty;
        const float* bsp = Bs + tx*8;
        #pragma unroll 8
        for (int ci = 0; ci < CI; ++ci) {
            ulonglong2 w01 = *(const ulonglong2*)(bsp + ci*64);
            ulonglong2 w23 = *(const ulonglong2*)(bsp + ci*64 + 4);
            unsigned long long xv[5];
            #pragma unroll
            for (int i = 0; i < 5; ++i)
                xv[i] = pack_dup(asp[ci*AS_PITCH + 16*i]);
            #pragma unroll
            for (int i = 0; i < 5; ++i) {
                acc[i][0] = ffma2(xv[i], w01.x, acc[i][0]);
                acc[i][1] = ffma2(xv[i], w01.y, acc[i][1]);
                acc[i][2] = ffma2(xv[i], w23.x, acc[i][2]);
                acc[i][3] = ffma2(xv[i], w23.y, acc[i][3]);
            }
        }
        __syncthreads();
    }

    // epilogue: + offset, ELU, hex mask, store valid cells (rest pre-zeroed)
    float ofs[8];
    #pragma unroll
    for (int j = 0; j < 8; ++j) ofs[j] = off[cb + tx*8 + j];

    const int di  = oh - 100;
    const int adi = di < 0 ? -di : di;

    #pragma unroll
    for (int i = 0; i < 5; ++i) {
        int owc = ty + 16*i;
        if (owc >= validw) continue;
        int ow  = 2*owc + p;
        int dj  = ow - 64;
        int adj = dj < 0 ? -dj : dj;
        if (adi + adj > 128) continue;   // outside hexagon -> stays zero

        float r[8];
        #pragma unroll
        for (int j = 0; j < 4; ++j) {
            float2 v = unpack2(acc[i][j]);
            r[2*j]   = v.x;
            r[2*j+1] = v.y;
        }
        #pragma unroll
        for (int j = 0; j < 8; ++j) {
            float v = r[j] + ofs[j];
            r[j] = v > 0.f ? v : expm1f(v);   // ELU (alpha=1)
        }
        float* dst = out + ((b*OH + oh)*OW + ow)*CO + cb + tx*8;
        *(float4*)dst       = make_float4(r[0], r[1], r[2], r[3]);
        *((float4*)dst + 1) = make_float4(r[4], r[5], r[6], r[7]);
    }
}

extern "C" void kernel_launch(void* const* d_in, const int* in_sizes, int n_in,
                              void* d_out, int out_size) {
    const float* x      = (const float*)d_in[0];   // [16,209,133,64]
    const float* sw     = (const float*)d_in[1];   // [19*64*128]
    const float* offset = (const float*)d_in[2];   // [128]
    float* out = (float*)d_out;

    // 1) zero full output (poisoned by harness; masked/odd-parity cells stay 0)
    zero_kernel<<<4096, 256>>>((float4*)out, OUT_ELEMS / 4);
    // 2) transpose weights -> wT[t][ci][co]
    prep_kernel<<<(NTAP*CI*CO + 255)/256, 256>>>(sw);
    // 3) main conv
    conv_kernel<<<dim3(OH, BATCH, 2), 128>>>(x, offset, out);
}

// round 3
// speedup vs baseline: 3.5524x; 3.5524x over previous
#include <cuda_runtime.h>
#include <cuda_bf16.h>
#include <cstdint>
#include <math.h>

#define BATCH 16
#define H 209
#define W 133
#define CI 64
#define CO 128
#define NTAP 19
#define OHH 201
#define OWW 129

// hex_indices(2) order (t matches sparse_weights layout) — validated in R1
__constant__ int c_dh[NTAP] = {4,3,5,6,5,3,2,1,2,4,6,7,8,7,6,4,2,1,0};
__constant__ int c_dw[NTAP] = {2,3,3,2,1,1,2,3,4,4,4,3,2,1,0,0,0,1,2};

// prepped weights: [t][co][ci] bf16, hi and lo planes
__device__ __nv_bfloat16 g_wh[NTAP*CO*CI];
__device__ __nv_bfloat16 g_wl[NTAP*CO*CI];

__device__ __forceinline__ uint32_t smem_u32(const void* p) {
    uint32_t a;
    asm("{ .reg .u64 t; cvta.to.shared.u64 t, %1; cvt.u32.u64 %0, t; }" : "=r"(a) : "l"(p));
    return a;
}
__device__ __forceinline__ uint32_t pack2bf(__nv_bfloat16 a, __nv_bfloat16 b) {
    return (uint32_t)__bfloat16_as_ushort(a) | ((uint32_t)__bfloat16_as_ushort(b) << 16);
}

#define LDSM4(r, addr)                                                          \
    asm volatile("ldmatrix.sync.aligned.m8n8.x4.shared.b16 {%0,%1,%2,%3}, [%4];"\
        : "=r"((r)[0]), "=r"((r)[1]), "=r"((r)[2]), "=r"((r)[3]) : "r"(addr))

#define MMA16816(c, a, b0, b1)                                                  \
    asm volatile("mma.sync.aligned.m16n8k16.row.col.f32.bf16.bf16.f32 "         \
        "{%0,%1,%2,%3}, {%4,%5,%6,%7}, {%8,%9}, {%0,%1,%2,%3};"                 \
        : "+f"((c)[0]), "+f"((c)[1]), "+f"((c)[2]), "+f"((c)[3])                \
        : "r"((a)[0]), "r"((a)[1]), "r"((a)[2]), "r"((a)[3]), "r"(b0), "r"(b1))

// ---------------- prep: split weights into bf16 hi/lo, layout [t][co][ci] ----------------
__global__ void prep_w_kernel(const float* __restrict__ sw) {
    int i = blockIdx.x * blockDim.x + threadIdx.x;
    if (i >= NTAP*CO*CI) return;
    int ci = i & 63;
    int co = (i >> 6) & 127;
    int t  = i >> 13;
    float f = sw[(ci*CO + co)*NTAP + t];
    __nv_bfloat16 h = __float2bfloat16_rn(f);
    g_wh[i] = h;
    g_wl[i] = __float2bfloat16_rn(f - __bfloat162float(h));
}

// ---------------- main mma.sync kernel ----------------
// grid (101 row-pairs, 16 batch), 256 threads (8 warps: 2 M-halves x 4 N-quarters).
// Per-tap stage buffer 64KB: Ah @0, Al @16K, Bh @32K, Bl @48K; tiles 128 rows x 128B,
// SW128 swizzle. Double-buffered (128KB) + 512B for offsets.
#define STAGE_BYTES 65536
#define SMEM_TOTAL  (2*STAGE_BYTES + 512)

__global__ __launch_bounds__(256, 1)
void conv_mma_kernel(const float* __restrict__ x,
                     const float* __restrict__ off,
                     float* __restrict__ out) {
    extern __shared__ __align__(1024) char smem[];
    const uint32_t smem_base = smem_u32(smem);
    const int tid    = threadIdx.x;
    const int lane   = tid & 31;
    const int wid    = tid >> 5;
    const int warp_m = wid >> 2;       // 0..1
    const int warp_n = wid & 3;        // 0..3
    const int r0     = blockIdx.x * 2; // first output row of pair
    const int b      = blockIdx.y;

    float* s_off = (float*)(smem + 2*STAGE_BYTES);
    if (tid < CO) s_off[tid] = off[tid];

    const float* xb = x + (size_t)b * H * W * CI;

    // per-lane ldmatrix base offsets (swizzle xor masks are row%8 << 4)
    const int rowA   = warp_m*64 + (lane & 15);
    const int baseA  = rowA*128 + ((lane >> 4) & 1)*16;
    const uint32_t mA = (uint32_t)(rowA & 7) << 4;
    const int rowB   = warp_n*32 + (lane & 7) + ((lane >> 4) & 1)*8;
    const int baseB  = rowB*128 + ((lane >> 3) & 1)*16;
    const uint32_t mB0 = (uint32_t)(rowB & 7) << 4;        // q=0  (rows rowB)
    const uint32_t mB1 = (uint32_t)((rowB+16) & 7) << 4;   // q=1 adds 16 rows (same %8)
    (void)mB1; // rowB+16 ≡ rowB (mod 8) -> same mask

    float c[4][4][4];
    #pragma unroll
    for (int i = 0; i < 4; ++i)
        #pragma unroll
        for (int j = 0; j < 4; ++j)
            #pragma unroll
            for (int k = 0; k < 4; ++k) c[i][j][k] = 0.f;

    float4 aReg[8];
    uint4  bReg[8];

    // ---- load tap t's gmem data into registers ----
    auto load_regs = [&](int t) {
        const int dh = c_dh[t], dw = c_dw[t];
        #pragma unroll
        for (int i = 0; i < 8; ++i) {
            int e    = tid + i*256;          // 0..2047
            int lrow = e >> 10;
            int owc  = (e >> 4) & 63;
            int c4   = e & 15;
            int row  = r0 + lrow;
            int hrow = row + dh;
            int wb   = (row & 1) + dw;
            aReg[i] = make_float4(0.f, 0.f, 0.f, 0.f);
            if (hrow <= 208)
                aReg[i] = ((const float4*)(xb + ((size_t)hrow*W + wb)*CI))[owc*32 + c4];
        }
        const uint4* whp = (const uint4*)(g_wh + (size_t)t*CO*CI);
        const uint4* wlp = (const uint4*)(g_wl + (size_t)t*CO*CI);
        #pragma unroll
        for (int i = 0; i < 8; ++i) {
            int e = tid + i*256;             // 0..2047; first 1024 hi, next 1024 lo
            bReg[i] = (e < 1024) ? whp[e & 1023] : wlp[e & 1023];
        }
    };

    // ---- store registers into stage buffer ----
    auto store_stage = [&](char* buf) {
        #pragma unroll
        for (int i = 0; i < 8; ++i) {
            int e    = tid + i*256;
            int lrow = e >> 10;
            int owc  = (e >> 4) & 63;
            int c4   = e & 15;
            float4 v = aReg[i];
            __nv_bfloat16 h0 = __float2bfloat16_rn(v.x);
            __nv_bfloat16 h1 = __float2bfloat16_rn(v.y);
            __nv_bfloat16 h2 = __float2bfloat16_rn(v.z);
            __nv_bfloat16 h3 = __float2bfloat16_rn(v.w);
            __nv_bfloat16 l0 = __float2bfloat16_rn(v.x - __bfloat162float(h0));
            __nv_bfloat16 l1 = __float2bfloat16_rn(v.y - __bfloat162float(h1));
            __nv_bfloat16 l2 = __float2bfloat16_rn(v.z - __bfloat162float(h2));
            __nv_bfloat16 l3 = __float2bfloat16_rn(v.w - __bfloat162float(h3));
            int m = lrow*64 + owc;
            uint32_t o  = (uint32_t)(m*128 + c4*8);
            uint32_t so = o ^ ((o >> 3) & 0x70);
            *(uint2*)(buf + so)         = make_uint2(pack2bf(h0,h1), pack2bf(h2,h3));
            *(uint2*)(buf + 16384 + so) = make_uint2(pack2bf(l0,l1), pack2bf(l2,l3));
        }
        #pragma unroll
        for (int i = 0; i < 8; ++i) {
            int e     = tid + i*256;
            int plane = e >> 10;
            int idx   = e & 1023;
            int co    = idx >> 3;
            int c8    = idx & 7;
            uint32_t o  = (uint32_t)(co*128 + c8*16);
            uint32_t so = o ^ ((o >> 3) & 0x70);
            *(uint4*)(buf + 32768 + plane*16384 + so) = bReg[i];
        }
    };

    // ---- compute one tap from stage buffer ----
    auto compute = [&](uint32_t bufa) {
        #pragma unroll
        for (int ks = 0; ks < 4; ++ks) {
            uint32_t ah[4][4], al[4][4], bh[2][4], bl[2][4];
            #pragma unroll
            for (int mt = 0; mt < 4; ++mt) {
                uint32_t o = (uint32_t)(baseA + mt*2048 + ks*32) ^ mA;
                LDSM4(ah[mt], bufa + o);
                LDSM4(al[mt], bufa + 16384 + o);
            }
            #pragma unroll
            for (int q = 0; q < 2; ++q) {
                uint32_t o = (uint32_t)(baseB + q*2048 + ks*32) ^ mB0;
                LDSM4(bh[q], bufa + 32768 + o);
                LDSM4(bl[q], bufa + 49152 + o);
            }
            #pragma unroll
            for (int mt = 0; mt < 4; ++mt)
                #pragma unroll
                for (int nt = 0; nt < 4; ++nt) {
                    int q = nt >> 1, h = (nt & 1)*2;
                    MMA16816(c[mt][nt], ah[mt], bh[q][h],   bh[q][h+1]);
                    MMA16816(c[mt][nt], al[mt], bh[q][h],   bh[q][h+1]);
                    MMA16816(c[mt][nt], ah[mt], bl[q][h],   bl[q][h+1]);
                }
        }
    };

    // ---- software pipeline over taps ----
    load_regs(0);
    store_stage(smem);
    __syncthreads();
    for (int t = 0; t < NTAP; ++t) {
        if (t + 1 < NTAP) load_regs(t + 1);
        compute(smem_base + (uint32_t)((t & 1) * STAGE_BYTES));
        __syncthreads();
        if (t + 1 < NTAP) {
            store_stage(smem + ((t + 1) & 1) * STAGE_BYTES);
            __syncthreads();
        }
    }

    // ---- epilogue: offset + ELU + hex mask, plus dead-parity-column zeros ----
    const int row = r0 + warp_m;
    if (row <= 200) {
        const int p   = row & 1;
        const int adi = row > 100 ? row - 100 : 100 - row;
        float* rbase  = out + ((size_t)(b*OHH + row) * OWW) * CO;
        const float2 z2 = make_float2(0.f, 0.f);
        const int co0 = warp_n*32 + (lane & 3)*2;
        #pragma unroll
        for (int mt = 0; mt < 4; ++mt) {
            #pragma unroll
            for (int hf = 0; hf < 2; ++hf) {
                int owc = mt*16 + (lane >> 2) + hf*8;
                int ow  = 2*owc + p;
                int owz = p ? (ow - 1) : (ow + 1);
                int adj = ow > 64 ? ow - 64 : 64 - ow;
                bool valid = (adi + adj) <= 128;
                float* vb = rbase + (size_t)ow  * CO;
                float* zb = rbase + (size_t)owz * CO;
                #pragma unroll
                for (int nt = 0; nt < 4; ++nt) {
                    int co = co0 + nt*8;
                    float v0 = c[mt][nt][hf*2+0] + s_off[co];
                    float v1 = c[mt][nt][hf*2+1] + s_off[co+1];
                    v0 = v0 > 0.f ? v0 : expm1f(v0);
                    v1 = v1 > 0.f ? v1 : expm1f(v1);
                    *(float2*)(vb + co) = valid ? make_float2(v0, v1) : z2;
                    *(float2*)(zb + co) = z2;
                }
            }
        }
    }
}

// ---------------- edge column ow=128 (even rows only can be valid) ----------------
__global__ void edge_kernel(const float* __restrict__ x,
                            const float* __restrict__ off,
                            float* __restrict__ out) {
    const int oh = blockIdx.x;
    const int b0 = blockIdx.y * 8;
    const int co = threadIdx.x;   // 128 threads
    const bool valid = ((oh & 1) == 0) && (oh >= 36) && (oh <= 164);
    if (!valid) {
        for (int bb = 0; bb < 8; ++bb)
            out[((size_t)((b0+bb)*OHH + oh)*OWW + 128)*CO + co] = 0.f;
        return;
    }
    __shared__ float xv[8*NTAP*CI];
    for (int e = threadIdx.x; e < 8*NTAP*CI; e += 128) {
        int bb = e / (NTAP*CI);
        int k  = e % (NTAP*CI);
        int t  = k >> 6, ci = k & 63;
        xv[e] = x[(((size_t)(b0+bb)*H + oh + c_dh[t])*W + 128 + c_dw[t])*CI + ci];
    }
    __syncthreads();
    float acc[8] = {0,0,0,0,0,0,0,0};
    for (int t = 0; t < NTAP; ++t) {
        const uint4* wh = (const uint4*)(g_wh + ((size_t)t*CO + co)*CI);
        const uint4* wl = (const uint4*)(g_wl + ((size_t)t*CO + co)*CI);
        #pragma unroll 2
        for (int g = 0; g < 8; ++g) {
            uint4 hv = wh[g], lv = wl[g];
            const __nv_bfloat16* hb = (const __nv_bfloat16*)&hv;
            const __nv_bfloat16* lb = (const __nv_bfloat16*)&lv;
            #pragma unroll
            for (int j = 0; j < 8; ++j) {
                float w = __bfloat162float(hb[j]) + __bfloat162float(lb[j]);
                #pragma unroll
                for (int bb = 0; bb < 8; ++bb)
                    acc[bb] = fmaf(w, xv[bb*NTAP*CI + t*CI + g*8 + j], acc[bb]);
            }
        }
    }
    float o = off[co];
    for (int bb = 0; bb < 8; ++bb) {
        float v = acc[bb] + o;
        v = v > 0.f ? v : expm1f(v);
        out[((size_t)((b0+bb)*OHH + oh)*OWW + 128)*CO + co] = v;
    }
}

extern "C" void kernel_launch(void* const* d_in, const int* in_sizes, int n_in,
                              void* d_out, int out_size) {
    const float* x      = (const float*)d_in[0];   // [16,209,133,64]
    const float* sw     = (const float*)d_in[1];   // [19*64*128] as [ci][co][t]
    const float* offset = (const float*)d_in[2];   // [128]
    float* out = (float*)d_out;

    cudaFuncSetAttribute(conv_mma_kernel,
                         cudaFuncAttributeMaxDynamicSharedMemorySize, SMEM_TOTAL);

    prep_w_kernel<<<(NTAP*CO*CI + 255)/256, 256>>>(sw);
    conv_mma_kernel<<<dim3(101, BATCH), 256, SMEM_TOTAL>>>(x, offset, out);
    edge_kernel<<<dim3(OHH, 2), 128>>>(x, offset, out);
}

// round 4
// speedup vs baseline: 4.1502x; 1.1683x over previous
#include <cuda_runtime.h>
#include <cuda_bf16.h>
#include <cstdint>
#include <math.h>

#define BATCH 16
#define H 209
#define W 133
#define CI 64
#define CO 128
#define NTAP 19
#define OHH 201
#define OWW 129
#define XELEMS (BATCH*H*W*CI)   // 28,462,592

// hex_indices(2) order (t matches sparse_weights layout) — validated in R1
__constant__ int c_dh[NTAP] = {4,3,5,6,5,3,2,1,2,4,6,7,8,7,6,4,2,1,0};
__constant__ int c_dw[NTAP] = {2,3,3,2,1,1,2,3,4,4,4,3,2,1,0,0,0,1,2};

// prepped weights: [t][co][ci] bf16, hi and lo planes
__device__ __align__(16) __nv_bfloat16 g_wh[NTAP*CO*CI];
__device__ __align__(16) __nv_bfloat16 g_wl[NTAP*CO*CI];
// prepped activations: x split into bf16 hi/lo, original NHWC layout
__device__ __align__(16) __nv_bfloat16 g_xh[XELEMS];
__device__ __align__(16) __nv_bfloat16 g_xl[XELEMS];

__device__ __forceinline__ uint32_t smem_u32(const void* p) {
    uint32_t a;
    asm("{ .reg .u64 t; cvta.to.shared.u64 t, %1; cvt.u32.u64 %0, t; }" : "=r"(a) : "l"(p));
    return a;
}
__device__ __forceinline__ uint32_t pack2bf(__nv_bfloat16 a, __nv_bfloat16 b) {
    return (uint32_t)__bfloat16_as_ushort(a) | ((uint32_t)__bfloat16_as_ushort(b) << 16);
}

#define LDSM4(r, addr)                                                          \
    asm volatile("ldmatrix.sync.aligned.m8n8.x4.shared.b16 {%0,%1,%2,%3}, [%4];"\
        : "=r"((r)[0]), "=r"((r)[1]), "=r"((r)[2]), "=r"((r)[3]) : "r"(addr))

#define MMA16816(c, a, b0, b1)                                                  \
    asm volatile("mma.sync.aligned.m16n8k16.row.col.f32.bf16.bf16.f32 "         \
        "{%0,%1,%2,%3}, {%4,%5,%6,%7}, {%8,%9}, {%0,%1,%2,%3};"                 \
        : "+f"((c)[0]), "+f"((c)[1]), "+f"((c)[2]), "+f"((c)[3])                \
        : "r"((a)[0]), "r"((a)[1]), "r"((a)[2]), "r"((a)[3]), "r"(b0), "r"(b1))

#define CP_ASYNC(dst, src, sz)                                                  \
    asm volatile("cp.async.cg.shared.global [%0], [%1], 16, %2;"                \
        :: "r"(dst), "l"(src), "r"(sz))
#define CP_COMMIT() asm volatile("cp.async.commit_group;" ::: "memory")
#define CP_WAIT(n)  asm volatile("cp.async.wait_group %0;" :: "n"(n) : "memory")

// ---------------- prep: split weights into bf16 hi/lo, layout [t][co][ci] ----------------
__global__ void prep_w_kernel(const float* __restrict__ sw) {
    int i = blockIdx.x * blockDim.x + threadIdx.x;
    if (i >= NTAP*CO*CI) return;
    int ci = i & 63;
    int co = (i >> 6) & 127;
    int t  = i >> 13;
    float f = sw[(ci*CO + co)*NTAP + t];
    __nv_bfloat16 h = __float2bfloat16_rn(f);
    g_wh[i] = h;
    g_wl[i] = __float2bfloat16_rn(f - __bfloat162float(h));
}

// ---------------- prep: split x into bf16 hi/lo planes (same NHWC layout) ----------------
__global__ void prep_x_kernel(const float* __restrict__ x) {
    int i = blockIdx.x * blockDim.x + threadIdx.x;   // float4 index
    if (i >= XELEMS/4) return;
    float4 v = ((const float4*)x)[i];
    __nv_bfloat16 h0 = __float2bfloat16_rn(v.x);
    __nv_bfloat16 h1 = __float2bfloat16_rn(v.y);
    __nv_bfloat16 h2 = __float2bfloat16_rn(v.z);
    __nv_bfloat16 h3 = __float2bfloat16_rn(v.w);
    __nv_bfloat16 l0 = __float2bfloat16_rn(v.x - __bfloat162float(h0));
    __nv_bfloat16 l1 = __float2bfloat16_rn(v.y - __bfloat162float(h1));
    __nv_bfloat16 l2 = __float2bfloat16_rn(v.z - __bfloat162float(h2));
    __nv_bfloat16 l3 = __float2bfloat16_rn(v.w - __bfloat162float(h3));
    ((uint2*)g_xh)[i] = make_uint2(pack2bf(h0,h1), pack2bf(h2,h3));
    ((uint2*)g_xl)[i] = make_uint2(pack2bf(l0,l1), pack2bf(l2,l3));
}

// ---------------- main mma.sync kernel ----------------
// grid (51 row-quads, 16 batch), 512 threads (16 warps: 4 M x 4 N).
// Stage buffer 96KB: Ah @0 (32K, 256 rows x 128B), Al @32K, Bh @64K (16K), Bl @80K.
// SW128 swizzle. Double-buffered via cp.async groups.
#define STAGE_BYTES 98304
#define SMEM_TOTAL  (2*STAGE_BYTES + 512)

__global__ __launch_bounds__(512, 1)
void conv_mma_kernel(const float* __restrict__ off, float* __restrict__ out) {
    extern __shared__ __align__(1024) char smem[];
    const uint32_t smem_base = smem_u32(smem);
    const int tid    = threadIdx.x;
    const int lane   = tid & 31;
    const int wid    = tid >> 5;
    const int warp_m = wid >> 2;       // 0..3
    const int warp_n = wid & 3;        // 0..3
    const int r0     = blockIdx.x * 4; // first output row of quad
    const int b      = blockIdx.y;

    float* s_off = (float*)(smem + 2*STAGE_BYTES);
    if (tid < CO) s_off[tid] = off[tid];

    const size_t xbase = (size_t)b * H * W * CI;

    // per-lane ldmatrix base offsets (swizzle xor masks are row%8 << 4)
    const int rowA   = warp_m*64 + (lane & 15);
    const int baseA  = rowA*128 + ((lane >> 4) & 1)*16;
    const uint32_t mA = (uint32_t)(rowA & 7) << 4;
    const int rowB   = warp_n*32 + (lane & 7) + ((lane >> 4) & 1)*8;
    const int baseB  = rowB*128 + ((lane >> 3) & 1)*16;
    const uint32_t mB = (uint32_t)(rowB & 7) << 4;   // +16 rows keeps same %8 mask

    float c[4][4][4];
    #pragma unroll
    for (int i = 0; i < 4; ++i)
        #pragma unroll
        for (int j = 0; j < 4; ++j)
            #pragma unroll
            for (int k = 0; k < 4; ++k) c[i][j][k] = 0.f;

    // ---- issue cp.async stage for tap t into buffer ----
    auto issue_cp = [&](int t, uint32_t bufa) {
        const int dh = c_dh[t], dw = c_dw[t];
        // A: 4096 chunks (256 m-rows x 8 c8 x 2 planes), exactly i=0..7
        #pragma unroll
        for (int i = 0; i < 8; ++i) {
            int e     = tid + i*512;
            int c8    = e & 7;
            int m     = (e >> 3) & 255;
            int plane = e >> 11;
            int lrow  = m >> 6;
            int owc   = m & 63;
            int row   = r0 + lrow;
            int hrow  = row + dh;
            int wb    = (row & 1) + dw;
            const __nv_bfloat16* src =
                (plane ? g_xl : g_xh) + xbase + ((size_t)hrow*W + wb + 2*owc)*CI + c8*8;
            uint32_t o = (uint32_t)(m*128 + c8*16);
            o ^= (o >> 3) & 0x70;
            int sz = (hrow <= 208) ? 16 : 0;
            CP_ASYNC(bufa + plane*32768 + o, src, sz);
        }
        // B: 2048 chunks (128 co x 8 c8 x 2 planes), i=8..11
        #pragma unroll
        for (int i = 8; i < 12; ++i) {
            int e     = tid + i*512 - 4096;
            int c8    = e & 7;
            int co    = (e >> 3) & 127;
            int plane = e >> 10;
            const __nv_bfloat16* src =
                (plane ? g_wl : g_wh) + (size_t)t*CO*CI + co*CI + c8*8;
            uint32_t o = (uint32_t)(co*128 + c8*16);
            o ^= (o >> 3) & 0x70;
            CP_ASYNC(bufa + 65536 + plane*16384 + o, src, 16);
        }
        CP_COMMIT();
    };

    // ---- compute one tap from stage buffer ----
    auto compute = [&](uint32_t bufa) {
        #pragma unroll
        for (int ks = 0; ks < 4; ++ks) {
            uint32_t bh[2][4], bl[2][4];
            #pragma unroll
            for (int q = 0; q < 2; ++q) {
                uint32_t o = (uint32_t)(baseB + q*2048 + ks*32) ^ mB;
                LDSM4(bh[q], bufa + 65536 + o);
                LDSM4(bl[q], bufa + 81920 + o);
            }
            #pragma unroll
            for (int mt = 0; mt < 4; ++mt) {
                uint32_t ah[4], al[4];
                uint32_t o = (uint32_t)(baseA + mt*2048 + ks*32) ^ mA;
                LDSM4(ah, bufa + o);
                LDSM4(al, bufa + 32768 + o);
                #pragma unroll
                for (int nt = 0; nt < 4; ++nt) {
                    int q = nt >> 1, h = (nt & 1)*2;
                    MMA16816(c[mt][nt], ah, bh[q][h], bh[q][h+1]);
                    MMA16816(c[mt][nt], al, bh[q][h], bh[q][h+1]);
                    MMA16816(c[mt][nt], ah, bl[q][h], bl[q][h+1]);
                }
            }
        }
    };

    // ---- pipelined tap loop ----
    issue_cp(0, smem_base);
    for (int t = 0; t < NTAP; ++t) {
        if (t + 1 < NTAP) issue_cp(t + 1, smem_base + ((t + 1) & 1)*STAGE_BYTES);
        if (t + 1 < NTAP) { CP_WAIT(1); } else { CP_WAIT(0); }
        __syncthreads();
        compute(smem_base + (t & 1)*STAGE_BYTES);
        __syncthreads();
    }

    // ---- epilogue: offset + ELU + hex mask, plus dead-parity-column zeros ----
    const int row = r0 + warp_m;
    if (row <= 200) {
        const int p   = row & 1;
        const int adi = row > 100 ? row - 100 : 100 - row;
        float* rbase  = out + ((size_t)(b*OHH + row) * OWW) * CO;
        const float2 z2 = make_float2(0.f, 0.f);
        const int co0 = warp_n*32 + (lane & 3)*2;
        #pragma unroll
        for (int mt = 0; mt < 4; ++mt) {
            #pragma unroll
            for (int hf = 0; hf < 2; ++hf) {
                int owc = mt*16 + (lane >> 2) + hf*8;
                int ow  = 2*owc + p;
                int owz = p ? (ow - 1) : (ow + 1);
                int adj = ow > 64 ? ow - 64 : 64 - ow;
                bool valid = (adi + adj) <= 128;
                float* vb = rbase + (size_t)ow  * CO;
                float* zb = rbase + (size_t)owz * CO;
                #pragma unroll
                for (int nt = 0; nt < 4; ++nt) {
                    int co = co0 + nt*8;
                    float v0 = c[mt][nt][hf*2+0] + s_off[co];
                    float v1 = c[mt][nt][hf*2+1] + s_off[co+1];
                    v0 = v0 > 0.f ? v0 : expm1f(v0);
                    v1 = v1 > 0.f ? v1 : expm1f(v1);
                    *(float2*)(vb + co) = valid ? make_float2(v0, v1) : z2;
                    *(float2*)(zb + co) = z2;
                }
            }
        }
    }
}

// ---------------- edge column ow=128 (even rows only can be valid) ----------------
__global__ void edge_kernel(const float* __restrict__ x,
                            const float* __restrict__ off,
                            float* __restrict__ out) {
    const int oh = blockIdx.x;
    const int b0 = blockIdx.y * 8;
    const int co = threadIdx.x;   // 128 threads
    const bool valid = ((oh & 1) == 0) && (oh >= 36) && (oh <= 164);
    if (!valid) {
        for (int bb = 0; bb < 8; ++bb)
            out[((size_t)((b0+bb)*OHH + oh)*OWW + 128)*CO + co] = 0.f;
        return;
    }
    __shared__ float xv[8*NTAP*CI];
    for (int e = threadIdx.x; e < 8*NTAP*CI; e += 128) {
        int bb = e / (NTAP*CI);
        int k  = e % (NTAP*CI);
        int t  = k >> 6, ci = k & 63;
        xv[e] = x[(((size_t)(b0+bb)*H + oh + c_dh[t])*W + 128 + c_dw[t])*CI + ci];
    }
    __syncthreads();
    float acc[8] = {0,0,0,0,0,0,0,0};
    for (int t = 0; t < NTAP; ++t) {
        const uint4* wh = (const uint4*)(g_wh + ((size_t)t*CO + co)*CI);
        const uint4* wl = (const uint4*)(g_wl + ((size_t)t*CO + co)*CI);
        #pragma unroll 2
        for (int g = 0; g < 8; ++g) {
            uint4 hv = wh[g], lv = wl[g];
            const __nv_bfloat16* hb = (const __nv_bfloat16*)&hv;
            const __nv_bfloat16* lb = (const __nv_bfloat16*)&lv;
            #pragma unroll
            for (int j = 0; j < 8; ++j) {
                float w = __bfloat162float(hb[j]) + __bfloat162float(lb[j]);
                #pragma unroll
                for (int bb = 0; bb < 8; ++bb)
                    acc[bb] = fmaf(w, xv[bb*NTAP*CI + t*CI + g*8 + j], acc[bb]);
            }
        }
    }
    float o = off[co];
    for (int bb = 0; bb < 8; ++bb) {
        float v = acc[bb] + o;
        v = v > 0.f ? v : expm1f(v);
        out[((size_t)((b0+bb)*OHH + oh)*OWW + 128)*CO + co] = v;
    }
}

extern "C" void kernel_launch(void* const* d_in, const int* in_sizes, int n_in,
                              void* d_out, int out_size) {
    const float* x      = (const float*)d_in[0];   // [16,209,133,64]
    const float* sw     = (const float*)d_in[1];   // [19*64*128] as [ci][co][t]
    const float* offset = (const float*)d_in[2];   // [128]
    float* out = (float*)d_out;

    cudaFuncSetAttribute(conv_mma_kernel,
                         cudaFuncAttributeMaxDynamicSharedMemorySize, SMEM_TOTAL);

    prep_w_kernel<<<(NTAP*CO*CI + 255)/256, 256>>>(sw);
    prep_x_kernel<<<(XELEMS/4 + 255)/256, 256>>>(x);
    conv_mma_kernel<<<dim3(51, BATCH), 512, SMEM_TOTAL>>>(offset, out);
    edge_kernel<<<dim3(OHH, 2), 128>>>(x, offset, out);
}

// round 5
// speedup vs baseline: 5.4887x; 1.3225x over previous
#include <cuda_runtime.h>
#include <cuda_fp16.h>
#include <cstdint>
#include <math.h>

#define BATCH 16
#define H 209
#define W 133
#define CI 64
#define CO 128
#define NTAP 19
#define OHH 201
#define OWW 129
#define XELEMS (BATCH*H*W*CI)   // 28,462,592

// hex_indices(2) order (t matches sparse_weights layout) — validated in R1
__constant__ int c_dh[NTAP] = {4,3,5,6,5,3,2,1,2,4,6,7,8,7,6,4,2,1,0};
__constant__ int c_dw[NTAP] = {2,3,3,2,1,1,2,3,4,4,4,3,2,1,0,0,0,1,2};

// prepped weights: [t][co][ci] fp16 (single plane; 2^-12 quantization)
__device__ __align__(16) __half g_w[NTAP*CO*CI];
// prepped activations: x split into fp16 hi/lo planes, original NHWC layout
__device__ __align__(16) __half g_xh[XELEMS];
__device__ __align__(16) __half g_xl[XELEMS];

__device__ __forceinline__ uint32_t smem_u32(const void* p) {
    uint32_t a;
    asm("{ .reg .u64 t; cvta.to.shared.u64 t, %1; cvt.u32.u64 %0, t; }" : "=r"(a) : "l"(p));
    return a;
}
__device__ __forceinline__ uint32_t pack2h(__half a, __half b) {
    return (uint32_t)__half_as_ushort(a) | ((uint32_t)__half_as_ushort(b) << 16);
}

#define LDSM4(r, addr)                                                          \
    asm volatile("ldmatrix.sync.aligned.m8n8.x4.shared.b16 {%0,%1,%2,%3}, [%4];"\
        : "=r"((r)[0]), "=r"((r)[1]), "=r"((r)[2]), "=r"((r)[3]) : "r"(addr))

#define MMA16816(c, a, b0, b1)                                                  \
    asm volatile("mma.sync.aligned.m16n8k16.row.col.f32.f16.f16.f32 "           \
        "{%0,%1,%2,%3}, {%4,%5,%6,%7}, {%8,%9}, {%0,%1,%2,%3};"                 \
        : "+f"((c)[0]), "+f"((c)[1]), "+f"((c)[2]), "+f"((c)[3])                \
        : "r"((a)[0]), "r"((a)[1]), "r"((a)[2]), "r"((a)[3]), "r"(b0), "r"(b1))

#define CP_ASYNC(dst, src, sz)                                                  \
    asm volatile("cp.async.cg.shared.global [%0], [%1], 16, %2;"                \
        :: "r"(dst), "l"(src), "r"(sz))
#define CP_COMMIT() asm volatile("cp.async.commit_group;" ::: "memory")
#define CP_WAIT(n)  asm volatile("cp.async.wait_group %0;" :: "n"(n) : "memory")

// ---------------- prep: quantize weights to fp16, layout [t][co][ci] ----------------
__global__ void prep_w_kernel(const float* __restrict__ sw) {
    int i = blockIdx.x * blockDim.x + threadIdx.x;
    if (i >= NTAP*CO*CI) return;
    int ci = i & 63;
    int co = (i >> 6) & 127;
    int t  = i >> 13;
    g_w[i] = __float2half_rn(sw[(ci*CO + co)*NTAP + t]);
}

// ---------------- prep: split x into fp16 hi/lo planes (same NHWC layout) ----------------
__global__ void prep_x_kernel(const float* __restrict__ x) {
    int i = blockIdx.x * blockDim.x + threadIdx.x;   // float4 index
    if (i >= XELEMS/4) return;
    float4 v = ((const float4*)x)[i];
    __half h0 = __float2half_rn(v.x);
    __half h1 = __float2half_rn(v.y);
    __half h2 = __float2half_rn(v.z);
    __half h3 = __float2half_rn(v.w);
    __half l0 = __float2half_rn(v.x - __half2float(h0));
    __half l1 = __float2half_rn(v.y - __half2float(h1));
    __half l2 = __float2half_rn(v.z - __half2float(h2));
    __half l3 = __float2half_rn(v.w - __half2float(h3));
    ((uint2*)g_xh)[i] = make_uint2(pack2h(h0,h1), pack2h(h2,h3));
    ((uint2*)g_xl)[i] = make_uint2(pack2h(l0,l1), pack2h(l2,l3));
}

// ---------------- main mma.sync kernel ----------------
// grid (51 row-quads, 16 batch), 512 threads (16 warps: 4 M x 4 N).
// Stage buffer 80KB: Ah @0 (32K, 256 rows x 128B), Al @32K, B @64K (16K).
// SW128 swizzle. Double-buffered via cp.async groups.
#define STAGE_BYTES 81920
#define SMEM_TOTAL  (2*STAGE_BYTES + 512)

__global__ __launch_bounds__(512, 1)
void conv_mma_kernel(const float* __restrict__ off, float* __restrict__ out) {
    extern __shared__ __align__(1024) char smem[];
    const uint32_t smem_base = smem_u32(smem);
    const int tid    = threadIdx.x;
    const int lane   = tid & 31;
    const int wid    = tid >> 5;
    const int warp_m = wid >> 2;       // 0..3
    const int warp_n = wid & 3;        // 0..3
    const int r0     = blockIdx.x * 4; // first output row of quad
    const int b      = blockIdx.y;

    float* s_off = (float*)(smem + 2*STAGE_BYTES);
    if (tid < CO) s_off[tid] = off[tid];

    const size_t xbase = (size_t)b * H * W * CI;

    // per-lane ldmatrix base offsets (swizzle xor masks are row%8 << 4)
    const int rowA   = warp_m*64 + (lane & 15);
    const int baseA  = rowA*128 + ((lane >> 4) & 1)*16;
    const uint32_t mA = (uint32_t)(rowA & 7) << 4;
    const int rowB   = warp_n*32 + (lane & 7) + ((lane >> 4) & 1)*8;
    const int baseB  = rowB*128 + ((lane >> 3) & 1)*16;
    const uint32_t mB = (uint32_t)(rowB & 7) << 4;   // +16 rows keeps same %8 mask

    float c[4][4][4];
    #pragma unroll
    for (int i = 0; i < 4; ++i)
        #pragma unroll
        for (int j = 0; j < 4; ++j)
            #pragma unroll
            for (int k = 0; k < 4; ++k) c[i][j][k] = 0.f;

    // ---- issue cp.async stage for tap t into buffer ----
    auto issue_cp = [&](int t, uint32_t bufa) {
        const int dh = c_dh[t], dw = c_dw[t];
        // A: 4096 chunks (256 m-rows x 8 c8 x 2 planes), i=0..7
        #pragma unroll
        for (int i = 0; i < 8; ++i) {
            int e     = tid + i*512;
            int c8    = e & 7;
            int m     = (e >> 3) & 255;
            int plane = e >> 11;
            int lrow  = m >> 6;
            int owc   = m & 63;
            int row   = r0 + lrow;
            int hrow  = row + dh;
            int wb    = (row & 1) + dw;
            const __half* src =
                (plane ? g_xl : g_xh) + xbase + ((size_t)hrow*W + wb + 2*owc)*CI + c8*8;
            uint32_t o = (uint32_t)(m*128 + c8*16);
            o ^= (o >> 3) & 0x70;
            int sz = (hrow <= 208) ? 16 : 0;
            CP_ASYNC(bufa + plane*32768 + o, src, sz);
        }
        // B: 1024 chunks (128 co x 8 c8), i=8..9
        #pragma unroll
        for (int i = 8; i < 10; ++i) {
            int e  = tid + (i-8)*512;
            int c8 = e & 7;
            int co = e >> 3;
            const __half* src = g_w + (size_t)t*CO*CI + co*CI + c8*8;
            uint32_t o = (uint32_t)(co*128 + c8*16);
            o ^= (o >> 3) & 0x70;
            CP_ASYNC(bufa + 65536 + o, src, 16);
        }
        CP_COMMIT();
    };

    // ---- compute one tap from stage buffer ----
    auto compute = [&](uint32_t bufa) {
        #pragma unroll
        for (int ks = 0; ks < 4; ++ks) {
            uint32_t bh[2][4];
            #pragma unroll
            for (int q = 0; q < 2; ++q) {
                uint32_t o = (uint32_t)(baseB + q*2048 + ks*32) ^ mB;
                LDSM4(bh[q], bufa + 65536 + o);
            }
            #pragma unroll
            for (int mt = 0; mt < 4; ++mt) {
                uint32_t ah[4], al[4];
                uint32_t o = (uint32_t)(baseA + mt*2048 + ks*32) ^ mA;
                LDSM4(ah, bufa + o);
                LDSM4(al, bufa + 32768 + o);
                #pragma unroll
                for (int nt = 0; nt < 4; ++nt) {
                    int q = nt >> 1, h = (nt & 1)*2;
                    MMA16816(c[mt][nt], ah, bh[q][h], bh[q][h+1]);
                    MMA16816(c[mt][nt], al, bh[q][h], bh[q][h+1]);
                }
            }
        }
    };

    // ---- pipelined tap loop ----
    issue_cp(0, smem_base);
    for (int t = 0; t < NTAP; ++t) {
        if (t + 1 < NTAP) issue_cp(t + 1, smem_base + ((t + 1) & 1)*STAGE_BYTES);
        if (t + 1 < NTAP) { CP_WAIT(1); } else { CP_WAIT(0); }
        __syncthreads();
        compute(smem_base + (t & 1)*STAGE_BYTES);
        __syncthreads();
    }

    // ---- epilogue: offset + ELU + hex mask, plus dead-parity-column zeros ----
    const int row = r0 + warp_m;
    if (row <= 200) {
        const int p   = row & 1;
        const int adi = row > 100 ? row - 100 : 100 - row;
        float* rbase  = out + ((size_t)(b*OHH + row) * OWW) * CO;
        const float2 z2 = make_float2(0.f, 0.f);
        const int co0 = warp_n*32 + (lane & 3)*2;
        #pragma unroll
        for (int mt = 0; mt < 4; ++mt) {
            #pragma unroll
            for (int hf = 0; hf < 2; ++hf) {
                int owc = mt*16 + (lane >> 2) + hf*8;
                int ow  = 2*owc + p;
                int owz = p ? (ow - 1) : (ow + 1);
                int adj = ow > 64 ? ow - 64 : 64 - ow;
                bool valid = (adi + adj) <= 128;
                float* vb = rbase + (size_t)ow  * CO;
                float* zb = rbase + (size_t)owz * CO;
                #pragma unroll
                for (int nt = 0; nt < 4; ++nt) {
                    int co = co0 + nt*8;
                    float v0 = c[mt][nt][hf*2+0] + s_off[co];
                    float v1 = c[mt][nt][hf*2+1] + s_off[co+1];
                    v0 = v0 > 0.f ? v0 : expm1f(v0);
                    v1 = v1 > 0.f ? v1 : expm1f(v1);
                    *(float2*)(vb + co) = valid ? make_float2(v0, v1) : z2;
                    *(float2*)(zb + co) = z2;
                }
            }
        }
    }
}

// ---------------- edge column ow=128 ----------------
// grid (201, 4): block = (oh, batch-quad). 128 threads (one co each).
// x staged as float4[k][bb] (broadcast LDS.128); w streamed from fp16 plane.
__global__ __launch_bounds__(128, 8)
void edge_kernel(const float* __restrict__ x,
                 const float* __restrict__ off,
                 float* __restrict__ out) {
    const int oh = blockIdx.x;
    const int b0 = blockIdx.y * 4;
    const int co = threadIdx.x;   // 128 threads
    const bool valid = ((oh & 1) == 0) && (oh >= 36) && (oh <= 164);
    if (!valid) {
        #pragma unroll
        for (int bb = 0; bb < 4; ++bb)
            out[((size_t)((b0+bb)*OHH + oh)*OWW + 128)*CO + co] = 0.f;
        return;
    }
    __shared__ float4 xv[NTAP*CI];   // [t*64+ci][bb]
    for (int e = threadIdx.x; e < NTAP*CI; e += 128) {
        int t = e >> 6, ci = e & 63;
        size_t base = ((size_t)(oh + c_dh[t])*W + 128 + c_dw[t])*CI + ci;
        float4 v;
        v.x = x[(size_t)(b0+0)*H*W*CI + base];
        v.y = x[(size_t)(b0+1)*H*W*CI + base];
        v.z = x[(size_t)(b0+2)*H*W*CI + base];
        v.w = x[(size_t)(b0+3)*H*W*CI + base];
        xv[e] = v;
    }
    __syncthreads();

    float a0 = 0.f, a1 = 0.f, a2 = 0.f, a3 = 0.f;
    for (int t = 0; t < NTAP; ++t) {
        const uint4* wp = (const uint4*)(g_w + ((size_t)t*CO + co)*CI);
        const float4* xp = xv + t*CI;
        #pragma unroll 2
        for (int g = 0; g < 8; ++g) {
            uint4 hv = wp[g];
            const __half* hb = (const __half*)&hv;
            #pragma unroll
            for (int j = 0; j < 8; ++j) {
                float w = __half2float(hb[j]);
                float4 xx = xp[g*8 + j];
                a0 = fmaf(w, xx.x, a0);
                a1 = fmaf(w, xx.y, a1);
                a2 = fmaf(w, xx.z, a2);
                a3 = fmaf(w, xx.w, a3);
            }
        }
    }
    float o = off[co];
    float r[4] = {a0 + o, a1 + o, a2 + o, a3 + o};
    #pragma unroll
    for (int bb = 0; bb < 4; ++bb) {
        float v = r[bb] > 0.f ? r[bb] : expm1f(r[bb]);
        out[((size_t)((b0+bb)*OHH + oh)*OWW + 128)*CO + co] = v;
    }
}

extern "C" void kernel_launch(void* const* d_in, const int* in_sizes, int n_in,
                              void* d_out, int out_size) {
    const float* x      = (const float*)d_in[0];   // [16,209,133,64]
    const float* sw     = (const float*)d_in[1];   // [19*64*128] as [ci][co][t]
    const float* offset = (const float*)d_in[2];   // [128]
    float* out = (float*)d_out;

    cudaFuncSetAttribute(conv_mma_kernel,
                         cudaFuncAttributeMaxDynamicSharedMemorySize, SMEM_TOTAL);

    prep_w_kernel<<<(NTAP*CO*CI + 255)/256, 256>>>(sw);
    prep_x_kernel<<<(XELEMS/4 + 255)/256, 256>>>(x);
    conv_mma_kernel<<<dim3(51, BATCH), 512, SMEM_TOTAL>>>(offset, out);
    edge_kernel<<<dim3(OHH, 4), 128>>>(x, offset, out);
}

// round 6
// speedup vs baseline: 9.3051x; 1.6953x over previous
#include <cuda_runtime.h>
#include <cuda_fp16.h>
#include <cstdint>
#include <math.h>

#define BATCH 16
#define H 209
#define W 133
#define CI 64
#define CO 128
#define NTAP 19
#define OHH 201
#define OWW 129
#define XELEMS (BATCH*H*W*CI)   // 28,462,592

// hex_indices(2) order (t matches sparse_weights layout) — validated in R1
__constant__ int c_dh[NTAP] = {4,3,5,6,5,3,2,1,2,4,6,7,8,7,6,4,2,1,0};
__constant__ int c_dw[NTAP] = {2,3,3,2,1,1,2,3,4,4,4,3,2,1,0,0,0,1,2};

// prepped weights: [t][co][ci] fp16
__device__ __align__(16) __half g_w[NTAP*CO*CI];
// prepped activations: fp16, original NHWC layout
__device__ __align__(16) __half g_x[XELEMS];

__device__ __forceinline__ uint32_t smem_u32(const void* p) {
    uint32_t a;
    asm("{ .reg .u64 t; cvta.to.shared.u64 t, %1; cvt.u32.u64 %0, t; }" : "=r"(a) : "l"(p));
    return a;
}
__device__ __forceinline__ uint32_t pack2h(__half a, __half b) {
    return (uint32_t)__half_as_ushort(a) | ((uint32_t)__half_as_ushort(b) << 16);
}

#define LDSM4(r, addr)                                                          \
    asm volatile("ldmatrix.sync.aligned.m8n8.x4.shared.b16 {%0,%1,%2,%3}, [%4];"\
        : "=r"((r)[0]), "=r"((r)[1]), "=r"((r)[2]), "=r"((r)[3]) : "r"(addr))

#define MMA16816(c, a, b0, b1)                                                  \
    asm volatile("mma.sync.aligned.m16n8k16.row.col.f32.f16.f16.f32 "           \
        "{%0,%1,%2,%3}, {%4,%5,%6,%7}, {%8,%9}, {%0,%1,%2,%3};"                 \
        : "+f"((c)[0]), "+f"((c)[1]), "+f"((c)[2]), "+f"((c)[3])                \
        : "r"((a)[0]), "r"((a)[1]), "r"((a)[2]), "r"((a)[3]), "r"(b0), "r"(b1))

#define CP_ASYNC(dst, src, sz)                                                  \
    asm volatile("cp.async.cg.shared.global [%0], [%1], 16, %2;"                \
        :: "r"(dst), "l"(src), "r"(sz))
#define CP_COMMIT() asm volatile("cp.async.commit_group;" ::: "memory")
#define CP_WAIT(n)  asm volatile("cp.async.wait_group %0;" :: "n"(n) : "memory")

// ---------------- prep kernels ----------------
__global__ void prep_w_kernel(const float* __restrict__ sw) {
    int i = blockIdx.x * blockDim.x + threadIdx.x;
    if (i >= NTAP*CO*CI) return;
    int ci = i & 63;
    int co = (i >> 6) & 127;
    int t  = i >> 13;
    g_w[i] = __float2half_rn(sw[(ci*CO + co)*NTAP + t]);
}

__global__ void prep_x_kernel(const float* __restrict__ x) {
    int i = blockIdx.x * blockDim.x + threadIdx.x;   // float4 index
    if (i >= XELEMS/4) return;
    float4 v = ((const float4*)x)[i];
    ((uint2*)g_x)[i] = make_uint2(
        pack2h(__float2half_rn(v.x), __float2half_rn(v.y)),
        pack2h(__float2half_rn(v.z), __float2half_rn(v.w)));
}

// ---------------- main mma.sync kernel ----------------
// grid (52, 16), 512 threads (16 warps: 4 M x 4 N).
// blockIdx.x < 51 : conv tile, 4 output rows x 64 owc (M=256), N=128 co.
// blockIdx.x == 51: edge column ow=128 for batch b — M=256 tile over even rows
//                   oh=2m (m<=100 live), same K loop; plus column-128 zero pass.
// Stage: A @0 (32KB: 256 rows x 128B), B @32K (16KB). SW128. 4-deep ring.
#define STAGE_BYTES 49152
#define NSTAGE 4
#define SMEM_TOTAL  (NSTAGE*STAGE_BYTES + 512)

__global__ __launch_bounds__(512, 1)
void conv_mma_kernel(const float* __restrict__ off, float* __restrict__ out) {
    extern __shared__ __align__(1024) char smem[];
    const uint32_t smem_base = smem_u32(smem);
    const int tid    = threadIdx.x;
    const int lane   = tid & 31;
    const int wid    = tid >> 5;
    const int warp_m = wid >> 2;       // 0..3
    const int warp_n = wid & 3;        // 0..3
    const int b      = blockIdx.y;
    const bool is_edge = (blockIdx.x == 51);
    const int r0     = blockIdx.x * 4; // first output row (conv path)

    float* s_off = (float*)(smem + NSTAGE*STAGE_BYTES);
    if (tid < CO) s_off[tid] = off[tid];

    // edge blocks: zero the whole ow=128 column for this batch up front
    if (is_edge) {
        for (int e = tid; e < OHH*CO; e += 512) {
            int oh = e >> 7, co = e & 127;
            out[((size_t)(b*OHH + oh)*OWW + 128)*CO + co] = 0.f;
        }
    }

    const size_t xbase = (size_t)b * H * W * CI;

    // per-lane ldmatrix base offsets (swizzle xor masks are row%8 << 4)
    const int rowA   = warp_m*64 + (lane & 15);
    const int baseA  = rowA*128 + ((lane >> 4) & 1)*16;
    const uint32_t mA = (uint32_t)(rowA & 7) << 4;
    const int rowB   = warp_n*32 + (lane & 7) + ((lane >> 4) & 1)*8;
    const int baseB  = rowB*128 + ((lane >> 3) & 1)*16;
    const uint32_t mB = (uint32_t)(rowB & 7) << 4;   // +16 rows keeps same %8 mask

    float c[4][4][4];
    #pragma unroll
    for (int i = 0; i < 4; ++i)
        #pragma unroll
        for (int j = 0; j < 4; ++j)
            #pragma unroll
            for (int k = 0; k < 4; ++k) c[i][j][k] = 0.f;

    // ---- issue cp.async stage for tap t into buffer ----
    auto issue_cp = [&](int t, uint32_t bufa) {
        const int dh = c_dh[t], dw = c_dw[t];
        // A: 2048 chunks (256 m-rows x 8 c8), i=0..3
        #pragma unroll
        for (int i = 0; i < 4; ++i) {
            int e  = tid + i*512;
            int c8 = e & 7;
            int m  = e >> 3;            // 0..255
            size_t soff; int sz;
            if (!is_edge) {
                int lrow = m >> 6;
                int owc  = m & 63;
                int row  = r0 + lrow;
                int hrow = row + dh;
                sz = (hrow <= 208) ? 16 : 0;
                if (!sz) hrow = 0;
                soff = ((size_t)hrow*W + (row & 1) + dw + 2*owc)*CI;
            } else {
                sz = (m <= 100) ? 16 : 0;
                int oh = sz ? 2*m : 0;
                soff = ((size_t)(oh + dh)*W + 128 + dw)*CI;
            }
            uint32_t o = (uint32_t)(m*128 + c8*16);
            o ^= (o >> 3) & 0x70;
            CP_ASYNC(bufa + o, g_x + xbase + soff + c8*8, sz);
        }
        // B: 1024 chunks (128 co x 8 c8), i=4..5
        #pragma unroll
        for (int i = 4; i < 6; ++i) {
            int e  = tid + (i-4)*512;
            int c8 = e & 7;
            int co = e >> 3;
            const __half* src = g_w + (size_t)t*CO*CI + co*CI + c8*8;
            uint32_t o = (uint32_t)(co*128 + c8*16);
            o ^= (o >> 3) & 0x70;
            CP_ASYNC(bufa + 32768 + o, src, 16);
        }
        CP_COMMIT();
    };

    // ---- compute one tap from stage buffer ----
    auto compute = [&](uint32_t bufa) {
        #pragma unroll
        for (int ks = 0; ks < 4; ++ks) {
            uint32_t bh[2][4];
            #pragma unroll
            for (int q = 0; q < 2; ++q) {
                uint32_t o = (uint32_t)(baseB + q*2048 + ks*32) ^ mB;
                LDSM4(bh[q], bufa + 32768 + o);
            }
            #pragma unroll
            for (int mt = 0; mt < 4; ++mt) {
                uint32_t ah[4];
                uint32_t o = (uint32_t)(baseA + mt*2048 + ks*32) ^ mA;
                LDSM4(ah, bufa + o);
                #pragma unroll
                for (int nt = 0; nt < 4; ++nt) {
                    int q = nt >> 1, h = (nt & 1)*2;
                    MMA16816(c[mt][nt], ah, bh[q][h], bh[q][h+1]);
                }
            }
        }
    };

    // ---- pipelined tap loop (4-stage ring, 3 groups in flight) ----
    issue_cp(0, smem_base);
    issue_cp(1, smem_base + STAGE_BYTES);
    issue_cp(2, smem_base + 2*STAGE_BYTES);
    for (int t = 0; t < NTAP; ++t) {
        if (t + 3 < NTAP) {
            issue_cp(t + 3, smem_base + (uint32_t)(((t + 3) & 3)*STAGE_BYTES));
            CP_WAIT(3);
        } else {
            CP_WAIT(0);   // tail: ensure group t complete (conservative)
        }
        __syncthreads();
        compute(smem_base + (uint32_t)((t & 3)*STAGE_BYTES));
        __syncthreads();
    }

    // ---- epilogue ----
    const int co0 = warp_n*32 + (lane & 3)*2;
    if (!is_edge) {
        const int row = r0 + warp_m;
        if (row <= 200) {
            const int p   = row & 1;
            const int adi = row > 100 ? row - 100 : 100 - row;
            float* rbase  = out + ((size_t)(b*OHH + row) * OWW) * CO;
            const float2 z2 = make_float2(0.f, 0.f);
            #pragma unroll
            for (int mt = 0; mt < 4; ++mt) {
                #pragma unroll
                for (int hf = 0; hf < 2; ++hf) {
                    int owc = mt*16 + (lane >> 2) + hf*8;
                    int ow  = 2*owc + p;
                    int owz = p ? (ow - 1) : (ow + 1);
                    int adj = ow > 64 ? ow - 64 : 64 - ow;
                    bool valid = (adi + adj) <= 128;
                    float* vb = rbase + (size_t)ow  * CO;
                    float* zb = rbase + (size_t)owz * CO;
                    #pragma unroll
                    for (int nt = 0; nt < 4; ++nt) {
                        int co = co0 + nt*8;
                        float v0 = c[mt][nt][hf*2+0] + s_off[co];
                        float v1 = c[mt][nt][hf*2+1] + s_off[co+1];
                        v0 = v0 > 0.f ? v0 : expm1f(v0);
                        v1 = v1 > 0.f ? v1 : expm1f(v1);
                        *(float2*)(vb + co) = valid ? make_float2(v0, v1) : z2;
                        *(float2*)(zb + co) = z2;
                    }
                }
            }
        }
    } else {
        // edge: tile row m -> output row oh=2m, column ow=128.
        // hex-valid iff oh in [36,164] (adi<=64). Invalid cells already zeroed.
        #pragma unroll
        for (int mt = 0; mt < 4; ++mt) {
            #pragma unroll
            for (int hf = 0; hf < 2; ++hf) {
                int m  = warp_m*64 + mt*16 + (lane >> 2) + hf*8;
                int oh = 2*m;
                if (m <= 100 && oh >= 36 && oh <= 164) {
                    float* vb = out + ((size_t)(b*OHH + oh)*OWW + 128)*CO;
                    #pragma unroll
                    for (int nt = 0; nt < 4; ++nt) {
                        int co = co0 + nt*8;
                        float v0 = c[mt][nt][hf*2+0] + s_off[co];
                        float v1 = c[mt][nt][hf*2+1] + s_off[co+1];
                        v0 = v0 > 0.f ? v0 : expm1f(v0);
                        v1 = v1 > 0.f ? v1 : expm1f(v1);
                        *(float2*)(vb + co) = make_float2(v0, v1);
                    }
                }
            }
        }
    }
}

extern "C" void kernel_launch(void* const* d_in, const int* in_sizes, int n_in,
                              void* d_out, int out_size) {
    const float* x      = (const float*)d_in[0];   // [16,209,133,64]
    const float* sw     = (const float*)d_in[1];   // [19*64*128] as [ci][co][t]
    const float* offset = (const float*)d_in[2];   // [128]
    float* out = (float*)d_out;

    cudaFuncSetAttribute(conv_mma_kernel,
                         cudaFuncAttributeMaxDynamicSharedMemorySize, SMEM_TOTAL);

    prep_w_kernel<<<(NTAP*CO*CI + 255)/256, 256>>>(sw);
    prep_x_kernel<<<(XELEMS/4 + 255)/256, 256>>>(x);
    conv_mma_kernel<<<dim3(52, BATCH), 512, SMEM_TOTAL>>>(offset, out);
}

// round 7
// speedup vs baseline: 10.0928x; 1.0846x over previous
#include <cuda_runtime.h>
#include <cuda_fp16.h>
#include <cstdint>
#include <math.h>

#define BATCH 16
#define H 209
#define W 133
#define CI 64
#define CO 128
#define NTAP 19
#define OHH 201
#define OWW 129
#define XELEMS (BATCH*H*W*CI)   // 28,462,592

// hex_indices(2) order (t matches sparse_weights layout) — validated in R1
__constant__ int c_dh[NTAP] = {4,3,5,6,5,3,2,1,2,4,6,7,8,7,6,4,2,1,0};
__constant__ int c_dw[NTAP] = {2,3,3,2,1,1,2,3,4,4,4,3,2,1,0,0,0,1,2};

// prepped weights: [t][co][ci] fp16
__device__ __align__(16) __half g_w[NTAP*CO*CI];
// prepped activations: fp16, original NHWC layout
__device__ __align__(16) __half g_x[XELEMS];

__device__ __forceinline__ uint32_t smem_u32(const void* p) {
    uint32_t a;
    asm("{ .reg .u64 t; cvta.to.shared.u64 t, %1; cvt.u32.u64 %0, t; }" : "=r"(a) : "l"(p));
    return a;
}
__device__ __forceinline__ uint32_t pack2h(__half a, __half b) {
    return (uint32_t)__half_as_ushort(a) | ((uint32_t)__half_as_ushort(b) << 16);
}

#define LDSM4(r, addr)                                                          \
    asm volatile("ldmatrix.sync.aligned.m8n8.x4.shared.b16 {%0,%1,%2,%3}, [%4];"\
        : "=r"((r)[0]), "=r"((r)[1]), "=r"((r)[2]), "=r"((r)[3]) : "r"(addr))

#define MMA16816(c, a, b0, b1)                                                  \
    asm volatile("mma.sync.aligned.m16n8k16.row.col.f32.f16.f16.f32 "           \
        "{%0,%1,%2,%3}, {%4,%5,%6,%7}, {%8,%9}, {%0,%1,%2,%3};"                 \
        : "+f"((c)[0]), "+f"((c)[1]), "+f"((c)[2]), "+f"((c)[3])                \
        : "r"((a)[0]), "r"((a)[1]), "r"((a)[2]), "r"((a)[3]), "r"(b0), "r"(b1))

#define CP_ASYNC(dst, src, sz)                                                  \
    asm volatile("cp.async.cg.shared.global [%0], [%1], 16, %2;"                \
        :: "r"(dst), "l"(src), "r"(sz))
#define CP_COMMIT() asm volatile("cp.async.commit_group;" ::: "memory")
#define CP_WAIT(n)  asm volatile("cp.async.wait_group %0;" :: "n"(n) : "memory")

// ---------------- prep kernels ----------------
__global__ void prep_w_kernel(const float* __restrict__ sw) {
    int i = blockIdx.x * blockDim.x + threadIdx.x;
    if (i >= NTAP*CO*CI) return;
    int ci = i & 63;
    int co = (i >> 6) & 127;
    int t  = i >> 13;
    g_w[i] = __float2half_rn(sw[(ci*CO + co)*NTAP + t]);
}

__global__ void prep_x_kernel(const float* __restrict__ x) {
    int i = blockIdx.x * blockDim.x + threadIdx.x;   // float4 index
    if (i >= XELEMS/4) return;
    float4 v = ((const float4*)x)[i];
    ((uint2*)g_x)[i] = make_uint2(
        pack2h(__float2half_rn(v.x), __float2half_rn(v.y)),
        pack2h(__float2half_rn(v.z), __float2half_rn(v.w)));
}

// ---------------- main mma.sync kernel ----------------
// grid (52, 16), 512 threads (16 warps: 4 M x 4 N).
// conv CTAs: parity-compacted x slab resident (12 rows x 68 wc x 128B = 104448B),
//            staged ONCE; per tap only B (16KB) staged into a 4-deep ring.
// edge CTA (blockIdx.x==51): per-tap A tile (32KB, 3-slot ring inside slab area).
#define SLAB_WC     68
#define SLAB_SLOTS  (12*SLAB_WC)        // 816
#define SLAB_BYTES  (SLAB_SLOTS*128)    // 104448
#define BOFF        SLAB_BYTES
#define SMEM_TOTAL  (SLAB_BYTES + 4*16384 + 512)   // 170496

__global__ __launch_bounds__(512, 1)
void conv_mma_kernel(const float* __restrict__ off, float* __restrict__ out) {
    extern __shared__ __align__(1024) char smem[];
    const uint32_t smem_base = smem_u32(smem);
    const int tid    = threadIdx.x;
    const int lane   = tid & 31;
    const int wid    = tid >> 5;
    const int warp_m = wid >> 2;       // 0..3
    const int warp_n = wid & 3;        // 0..3
    const int b      = blockIdx.y;
    const bool is_edge = (blockIdx.x == 51);
    const int r0     = blockIdx.x * 4; // first output row (conv path)

    float* s_off = (float*)(smem + SMEM_TOTAL - 512);
    if (tid < CO) s_off[tid] = off[tid];

    if (is_edge) {
        for (int e = tid; e < OHH*CO; e += 512) {
            int oh = e >> 7, co = e & 127;
            out[((size_t)(b*OHH + oh)*OWW + 128)*CO + co] = 0.f;
        }
    }

    const size_t xbase = (size_t)b * H * W * CI;

    // per-lane pieces of A/B ldmatrix addressing
    const uint32_t laneoA = (uint32_t)((lane & 15)*128 + ((lane >> 4) & 1)*16);
    const int rowB   = warp_n*32 + (lane & 7) + ((lane >> 4) & 1)*8;
    const uint32_t baseB = (uint32_t)(rowB*128 + ((lane >> 3) & 1)*16);
    const uint32_t mB = (uint32_t)(rowB & 7) << 4;

    float c[4][4][4];
    #pragma unroll
    for (int i = 0; i < 4; ++i)
        #pragma unroll
        for (int j = 0; j < 4; ++j)
            #pragma unroll
            for (int k = 0; k < 4; ++k) c[i][j][k] = 0.f;

    // ---- B stage for tap t into ring slot t&3 ----
    auto issue_B = [&](int t) {
        uint32_t bufa = smem_base + BOFF + (uint32_t)((t & 3)*16384);
        #pragma unroll
        for (int i = 0; i < 2; ++i) {
            int e  = tid + i*512;
            int c8 = e & 7;
            int co = e >> 3;
            uint32_t o = (uint32_t)(co*128 + c8*16);
            o ^= (o >> 3) & 0x70;
            CP_ASYNC(bufa + o, g_w + (size_t)t*CO*CI + co*CI + c8*8, 16);
        }
    };

    // ---- edge A tile for tap t into 3-slot ring (inside slab area) ----
    auto issue_A_edge = [&](int t) {
        uint32_t bufa = smem_base + (uint32_t)((t % 3)*32768);
        const int dh = c_dh[t], dw = c_dw[t];
        #pragma unroll
        for (int i = 0; i < 4; ++i) {
            int e  = tid + i*512;
            int c8 = e & 7;
            int m  = e >> 3;
            int sz = (m <= 100) ? 16 : 0;
            int oh = sz ? 2*m : 0;
            size_t soff = ((size_t)(oh + dh)*W + 128 + dw)*CI + c8*8;
            uint32_t o = (uint32_t)(m*128 + c8*16);
            o ^= (o >> 3) & 0x70;
            CP_ASYNC(bufa + o, g_x + xbase + soff, sz);
        }
    };

    // ---- compute one tap: A rows at rbase + owc in bufA, B in bufB ----
    auto compute = [&](uint32_t bufA, int rbase, uint32_t bufB) {
        const uint32_t maskA  = (uint32_t)(((rbase + (lane & 15)) & 7) << 4);
        const uint32_t baseoA = (uint32_t)(rbase*128) + laneoA;
        #pragma unroll
        for (int ks = 0; ks < 4; ++ks) {
            uint32_t bh[2][4];
            #pragma unroll
            for (int q = 0; q < 2; ++q)
                LDSM4(bh[q], bufB + ((baseB + q*2048 + ks*32) ^ mB));
            #pragma unroll
            for (int mt = 0; mt < 4; ++mt) {
                uint32_t ah[4];
                LDSM4(ah, bufA + ((baseoA + (uint32_t)(mt*2048 + ks*32)) ^ maskA));
                #pragma unroll
                for (int nt = 0; nt < 4; ++nt) {
                    int q = nt >> 1, h = (nt & 1)*2;
                    MMA16816(c[mt][nt], ah, bh[q][h], bh[q][h+1]);
                }
            }
        }
    };

    if (!is_edge) {
        // ---- stage the whole parity-compacted slab once (group 0) ----
        for (int e = tid; e < SLAB_SLOTS*8; e += 512) {
            int c8   = e & 7;
            int slot = e >> 3;               // 0..815
            int hr   = slot / SLAB_WC;
            int wc   = slot - hr*SLAB_WC;
            int hrow = r0 + hr;
            int w    = 2*wc + (hrow & 1);
            int sz   = (hrow <= 208 && w <= 132) ? 16 : 0;
            size_t soff = sz ? (((size_t)hrow*W + w)*CI + c8*8) : 0;
            uint32_t o = (uint32_t)(slot*128 + c8*16);
            o ^= (o >> 3) & 0x70;
            CP_ASYNC(smem_base + o, g_x + xbase + soff, sz);
        }
        CP_COMMIT();
        issue_B(0); CP_COMMIT();
        issue_B(1); CP_COMMIT();
        issue_B(2); CP_COMMIT();

        const int rp = (r0 + warp_m) & 1;
        for (int t = 0; t < NTAP; ++t) {
            if (t + 3 < NTAP)      { issue_B(t + 3); CP_COMMIT(); CP_WAIT(3); }
            else if (t == NTAP-3)  { CP_WAIT(2); }
            else if (t == NTAP-2)  { CP_WAIT(1); }
            else                   { CP_WAIT(0); }
            __syncthreads();
            const int dh = c_dh[t], dw = c_dw[t];
            const int hp = (rp + dh) & 1;
            const int wc0 = (rp + dw - hp) >> 1;
            compute(smem_base, (warp_m + dh)*SLAB_WC + wc0,
                    smem_base + BOFF + (uint32_t)((t & 3)*16384));
            __syncthreads();
        }

        // ---- conv epilogue ----
        const int co0 = warp_n*32 + (lane & 3)*2;
        const int row = r0 + warp_m;
        if (row <= 200) {
            const int p   = row & 1;
            const int adi = row > 100 ? row - 100 : 100 - row;
            float* rbaseo = out + ((size_t)(b*OHH + row) * OWW) * CO;
            const float2 z2 = make_float2(0.f, 0.f);
            #pragma unroll
            for (int mt = 0; mt < 4; ++mt) {
                #pragma unroll
                for (int hf = 0; hf < 2; ++hf) {
                    int owc = mt*16 + (lane >> 2) + hf*8;
                    int ow  = 2*owc + p;
                    int owz = p ? (ow - 1) : (ow + 1);
                    int adj = ow > 64 ? ow - 64 : 64 - ow;
                    bool valid = (adi + adj) <= 128;
                    float* vb = rbaseo + (size_t)ow  * CO;
                    float* zb = rbaseo + (size_t)owz * CO;
                    #pragma unroll
                    for (int nt = 0; nt < 4; ++nt) {
                        int co = co0 + nt*8;
                        float v0 = c[mt][nt][hf*2+0] + s_off[co];
                        float v1 = c[mt][nt][hf*2+1] + s_off[co+1];
                        v0 = v0 > 0.f ? v0 : expm1f(v0);
                        v1 = v1 > 0.f ? v1 : expm1f(v1);
                        *(float2*)(vb + co) = valid ? make_float2(v0, v1) : z2;
                        *(float2*)(zb + co) = z2;
                    }
                }
            }
        }
    } else {
        issue_A_edge(0); issue_B(0); CP_COMMIT();
        issue_A_edge(1); issue_B(1); CP_COMMIT();
        for (int t = 0; t < NTAP; ++t) {
            if (t + 2 < NTAP)      { issue_A_edge(t+2); issue_B(t+2); CP_COMMIT(); CP_WAIT(2); }
            else if (t == NTAP-2)  { CP_WAIT(1); }
            else                   { CP_WAIT(0); }
            __syncthreads();
            compute(smem_base + (uint32_t)((t % 3)*32768), warp_m*64,
                    smem_base + BOFF + (uint32_t)((t & 3)*16384));
            __syncthreads();
        }

        // ---- edge epilogue: row m -> oh=2m, ow=128; valid iff oh in [36,164] ----
        const int co0 = warp_n*32 + (lane & 3)*2;
        #pragma unroll
        for (int mt = 0; mt < 4; ++mt) {
            #pragma unroll
            for (int hf = 0; hf < 2; ++hf) {
                int m  = warp_m*64 + mt*16 + (lane >> 2) + hf*8;
                int oh = 2*m;
                if (m <= 100 && oh >= 36 && oh <= 164) {
                    float* vb = out + ((size_t)(b*OHH + oh)*OWW + 128)*CO;
                    #pragma unroll
                    for (int nt = 0; nt < 4; ++nt) {
                        int co = co0 + nt*8;
                        float v0 = c[mt][nt][hf*2+0] + s_off[co];
                        float v1 = c[mt][nt][hf*2+1] + s_off[co+1];
                        v0 = v0 > 0.f ? v0 : expm1f(v0);
                        v1 = v1 > 0.f ? v1 : expm1f(v1);
                        *(float2*)(vb + co) = make_float2(v0, v1);
                    }
                }
            }
        }
    }
}

extern "C" void kernel_launch(void* const* d_in, const int* in_sizes, int n_in,
                              void* d_out, int out_size) {
    const float* x      = (const float*)d_in[0];   // [16,209,133,64]
    const float* sw     = (const float*)d_in[1];   // [19*64*128] as [ci][co][t]
    const float* offset = (const float*)d_in[2];   // [128]
    float* out = (float*)d_out;

    cudaFuncSetAttribute(conv_mma_kernel,
                         cudaFuncAttributeMaxDynamicSharedMemorySize, SMEM_TOTAL);

    prep_w_kernel<<<(NTAP*CO*CI + 255)/256, 256>>>(sw);
    prep_x_kernel<<<(XELEMS/4 + 255)/256, 256>>>(x);
    conv_mma_kernel<<<dim3(52, BATCH), 512, SMEM_TOTAL>>>(offset, out);
}

// round 8
// speedup vs baseline: 10.4797x; 1.0383x over previous
#include <cuda_runtime.h>
#include <cuda_fp16.h>
#include <cstdint>
#include <math.h>

#define BATCH 16
#define H 209
#define W 133
#define CI 64
#define CO 128
#define NTAP 19
#define OHH 201
#define OWW 129

// hex_indices(2) order (t matches sparse_weights layout) — validated in R1
__constant__ int c_dh[NTAP] = {4,3,5,6,5,3,2,1,2,4,6,7,8,7,6,4,2,1,0};
__constant__ int c_dw[NTAP] = {2,3,3,2,1,1,2,3,4,4,4,3,2,1,0,0,0,1,2};

// prepped weights: [t][co][ci] fp16
__device__ __align__(16) __half g_w[NTAP*CO*CI];

__device__ __forceinline__ uint32_t smem_u32(const void* p) {
    uint32_t a;
    asm("{ .reg .u64 t; cvta.to.shared.u64 t, %1; cvt.u32.u64 %0, t; }" : "=r"(a) : "l"(p));
    return a;
}
__device__ __forceinline__ uint32_t pack2h(__half a, __half b) {
    return (uint32_t)__half_as_ushort(a) | ((uint32_t)__half_as_ushort(b) << 16);
}
__device__ __forceinline__ uint2 cvt4(float4 v) {
    return make_uint2(pack2h(__float2half_rn(v.x), __float2half_rn(v.y)),
                      pack2h(__float2half_rn(v.z), __float2half_rn(v.w)));
}

#define LDSM4(r, addr)                                                          \
    asm volatile("ldmatrix.sync.aligned.m8n8.x4.shared.b16 {%0,%1,%2,%3}, [%4];"\
        : "=r"((r)[0]), "=r"((r)[1]), "=r"((r)[2]), "=r"((r)[3]) : "r"(addr))

#define MMA16816(c, a, b0, b1)                                                  \
    asm volatile("mma.sync.aligned.m16n8k16.row.col.f32.f16.f16.f32 "           \
        "{%0,%1,%2,%3}, {%4,%5,%6,%7}, {%8,%9}, {%0,%1,%2,%3};"                 \
        : "+f"((c)[0]), "+f"((c)[1]), "+f"((c)[2]), "+f"((c)[3])                \
        : "r"((a)[0]), "r"((a)[1]), "r"((a)[2]), "r"((a)[3]), "r"(b0), "r"(b1))

#define CP_ASYNC(dst, src, sz)                                                  \
    asm volatile("cp.async.cg.shared.global [%0], [%1], 16, %2;"                \
        :: "r"(dst), "l"(src), "r"(sz))
#define CP_COMMIT() asm volatile("cp.async.commit_group;" ::: "memory")
#define CP_WAIT(n)  asm volatile("cp.async.wait_group %0;" :: "n"(n) : "memory")

// ---------------- prep: weights to fp16, layout [t][co][ci] ----------------
__global__ void prep_w_kernel(const float* __restrict__ sw) {
    int i = blockIdx.x * blockDim.x + threadIdx.x;
    if (i >= NTAP*CO*CI) return;
    int ci = i & 63;
    int co = (i >> 6) & 127;
    int t  = i >> 13;
    g_w[i] = __float2half_rn(sw[(ci*CO + co)*NTAP + t]);
}

// ---------------- main mma.sync kernel ----------------
// grid (52, 16), 512 threads (16 warps: 4 M x 4 N).
// conv CTAs: parity-compacted fp16 x-slab (12 rows x 68 wc x 128B = 104448B)
//            built ONCE from f32 x (inline cvt); per tap only B (16KB, 4-ring).
// edge CTA (blockIdx.x==51): per-tap A tile from f32 (32KB, 3-slot ring in slab area).
// ONE __syncthreads per tap.
#define SLAB_WC     68
#define SLAB_SLOTS  (12*SLAB_WC)        // 816
#define SLAB_BYTES  (SLAB_SLOTS*128)    // 104448
#define BOFF        SLAB_BYTES
#define SMEM_TOTAL  (SLAB_BYTES + 4*16384 + 512)   // 170496

__global__ __launch_bounds__(512, 1)
void conv_mma_kernel(const float* __restrict__ x,
                     const float* __restrict__ off, float* __restrict__ out) {
    extern __shared__ __align__(1024) char smem[];
    const uint32_t smem_base = smem_u32(smem);
    const int tid    = threadIdx.x;
    const int lane   = tid & 31;
    const int wid    = tid >> 5;
    const int warp_m = wid >> 2;       // 0..3
    const int warp_n = wid & 3;        // 0..3
    const int b      = blockIdx.y;
    const bool is_edge = (blockIdx.x == 51);
    const int r0     = blockIdx.x * 4; // first output row (conv path)

    float* s_off = (float*)(smem + SMEM_TOTAL - 512);
    if (tid < CO) s_off[tid] = off[tid];

    if (is_edge) {
        for (int e = tid; e < OHH*CO; e += 512) {
            int oh = e >> 7, co = e & 127;
            out[((size_t)(b*OHH + oh)*OWW + 128)*CO + co] = 0.f;
        }
    }

    const float* xb = x + (size_t)b * H * W * CI;

    // per-lane pieces of A/B ldmatrix addressing
    const uint32_t laneoA = (uint32_t)((lane & 15)*128 + ((lane >> 4) & 1)*16);
    const int rowB   = warp_n*32 + (lane & 7) + ((lane >> 4) & 1)*8;
    const uint32_t baseB = (uint32_t)(rowB*128 + ((lane >> 3) & 1)*16);
    const uint32_t mB = (uint32_t)(rowB & 7) << 4;

    float c[4][4][4];
    #pragma unroll
    for (int i = 0; i < 4; ++i)
        #pragma unroll
        for (int j = 0; j < 4; ++j)
            #pragma unroll
            for (int k = 0; k < 4; ++k) c[i][j][k] = 0.f;

    // ---- B stage for tap t into ring slot t&3 (cp.async, one group) ----
    auto issue_B = [&](int t) {
        uint32_t bufa = smem_base + BOFF + (uint32_t)((t & 3)*16384);
        #pragma unroll
        for (int i = 0; i < 2; ++i) {
            int e  = tid + i*512;
            int c8 = e & 7;
            int co = e >> 3;
            uint32_t o = (uint32_t)(co*128 + c8*16);
            o ^= (o >> 3) & 0x70;
            CP_ASYNC(bufa + o, g_w + (size_t)t*CO*CI + co*CI + c8*8, 16);
        }
        CP_COMMIT();
    };

    // ---- edge A tile for tap t: f32 LDG -> fp16 STS into 3-slot ring ----
    auto stage_A_edge = [&](int t) {
        char* bufp = smem + (t % 3)*32768;
        const int dh = c_dh[t], dw = c_dw[t];
        #pragma unroll
        for (int i = 0; i < 8; ++i) {
            int e  = tid + i*512;          // 0..4095: 256 m x 16 c4
            int c4 = e & 15;
            int m  = e >> 4;
            float4 v = make_float4(0.f,0.f,0.f,0.f);
            if (m <= 100)
                v = *(const float4*)(xb + ((size_t)(2*m + dh)*W + 128 + dw)*CI + c4*4);
            uint32_t o = (uint32_t)(m*128 + c4*8);
            o ^= (o >> 3) & 0x70;
            *(uint2*)(bufp + o) = cvt4(v);
        }
    };

    // ---- compute one tap: A rows at rbase + owc in bufA, B in bufB ----
    auto compute = [&](uint32_t bufA, int rbase, uint32_t bufB) {
        const uint32_t maskA  = (uint32_t)(((rbase + (lane & 15)) & 7) << 4);
        const uint32_t baseoA = (uint32_t)(rbase*128) + laneoA;
        #pragma unroll
        for (int ks = 0; ks < 4; ++ks) {
            uint32_t bh[2][4];
            #pragma unroll
            for (int q = 0; q < 2; ++q)
                LDSM4(bh[q], bufB + ((baseB + q*2048 + ks*32) ^ mB));
            #pragma unroll
            for (int mt = 0; mt < 4; ++mt) {
                uint32_t ah[4];
                LDSM4(ah, bufA + ((baseoA + (uint32_t)(mt*2048 + ks*32)) ^ maskA));
                #pragma unroll
                for (int nt = 0; nt < 4; ++nt) {
                    int q = nt >> 1, h = (nt & 1)*2;
                    MMA16816(c[mt][nt], ah, bh[q][h], bh[q][h+1]);
                }
            }
        }
    };

    if (!is_edge) {
        // ---- B ring prefill (3 groups) ----
        issue_B(0); issue_B(1); issue_B(2);

        // ---- build fp16 slab from f32 x (once) ----
        for (int e = tid; e < SLAB_SLOTS*16; e += 512) {
            int c4   = e & 15;
            int slot = e >> 4;               // 0..815
            int hr   = slot / SLAB_WC;
            int wc   = slot - hr*SLAB_WC;
            int hrow = r0 + hr;
            int w    = 2*wc + (hrow & 1);
            float4 v = make_float4(0.f,0.f,0.f,0.f);
            if (hrow <= 208 && w <= 132)
                v = *(const float4*)(xb + ((size_t)hrow*W + w)*CI + c4*4);
            uint32_t o = (uint32_t)(slot*128 + c4*8);
            o ^= (o >> 3) & 0x70;
            *(uint2*)(smem + o) = cvt4(v);
        }

        const int rp = (r0 + warp_m) & 1;
        for (int t = 0; t < NTAP; ++t) {
            if      (t + 3 < NTAP) { CP_WAIT(2); }
            else if (t == NTAP-3)  { CP_WAIT(2); }
            else if (t == NTAP-2)  { CP_WAIT(1); }
            else                   { CP_WAIT(0); }
            __syncthreads();
            const int dh = c_dh[t], dw = c_dw[t];
            const int hp = (rp + dh) & 1;
            const int wc0 = (rp + dw - hp) >> 1;
            compute(smem_base, (warp_m + dh)*SLAB_WC + wc0,
                    smem_base + BOFF + (uint32_t)((t & 3)*16384));
            if (t + 3 < NTAP) issue_B(t + 3);
        }

        // ---- conv epilogue ----
        const int co0 = warp_n*32 + (lane & 3)*2;
        const int row = r0 + warp_m;
        if (row <= 200) {
            const int p   = row & 1;
            const int adi = row > 100 ? row - 100 : 100 - row;
            float* rbaseo = out + ((size_t)(b*OHH + row) * OWW) * CO;
            const float2 z2 = make_float2(0.f, 0.f);
            #pragma unroll
            for (int mt = 0; mt < 4; ++mt) {
                #pragma unroll
                for (int hf = 0; hf < 2; ++hf) {
                    int owc = mt*16 + (lane >> 2) + hf*8;
                    int ow  = 2*owc + p;
                    int owz = p ? (ow - 1) : (ow + 1);
                    int adj = ow > 64 ? ow - 64 : 64 - ow;
                    bool valid = (adi + adj) <= 128;
                    float* vb = rbaseo + (size_t)ow  * CO;
                    float* zb = rbaseo + (size_t)owz * CO;
                    #pragma unroll
                    for (int nt = 0; nt < 4; ++nt) {
                        int co = co0 + nt*8;
                        float v0 = c[mt][nt][hf*2+0] + s_off[co];
                        float v1 = c[mt][nt][hf*2+1] + s_off[co+1];
                        v0 = v0 > 0.f ? v0 : expm1f(v0);
                        v1 = v1 > 0.f ? v1 : expm1f(v1);
                        *(float2*)(vb + co) = valid ? make_float2(v0, v1) : z2;
                        *(float2*)(zb + co) = z2;
                    }
                }
            }
        }
    } else {
        issue_B(0); issue_B(1);
        stage_A_edge(0); stage_A_edge(1);
        for (int t = 0; t < NTAP; ++t) {
            if      (t + 2 < NTAP) { CP_WAIT(1); }
            else if (t == NTAP-2)  { CP_WAIT(1); }
            else                   { CP_WAIT(0); }
            __syncthreads();
            compute(smem_base + (uint32_t)((t % 3)*32768), warp_m*64,
                    smem_base + BOFF + (uint32_t)((t & 3)*16384));
            if (t + 2 < NTAP) { issue_B(t + 2); stage_A_edge(t + 2); }
        }

        // ---- edge epilogue: row m -> oh=2m, ow=128; valid iff oh in [36,164] ----
        const int co0 = warp_n*32 + (lane & 3)*2;
        #pragma unroll
        for (int mt = 0; mt < 4; ++mt) {
            #pragma unroll
            for (int hf = 0; hf < 2; ++hf) {
                int m  = warp_m*64 + mt*16 + (lane >> 2) + hf*8;
                int oh = 2*m;
                if (m <= 100 && oh >= 36 && oh <= 164) {
                    float* vb = out + ((size_t)(b*OHH + oh)*OWW + 128)*CO;
                    #pragma unroll
                    for (int nt = 0; nt < 4; ++nt) {
                        int co = co0 + nt*8;
                        float v0 = c[mt][nt][hf*2+0] + s_off[co];
                        float v1 = c[mt][nt][hf*2+1] + s_off[co+1];
                        v0 = v0 > 0.f ? v0 : expm1f(v0);
                        v1 = v1 > 0.f ? v1 : expm1f(v1);
                        *(float2*)(vb + co) = make_float2(v0, v1);
                    }
                }
            }
        }
    }
}

extern "C" void kernel_launch(void* const* d_in, const int* in_sizes, int n_in,
                              void* d_out, int out_size) {
    const float* x      = (const float*)d_in[0];   // [16,209,133,64]
    const float* sw     = (const float*)d_in[1];   // [19*64*128] as [ci][co][t]
    const float* offset = (const float*)d_in[2];   // [128]
    float* out = (float*)d_out;

    cudaFuncSetAttribute(conv_mma_kernel,
                         cudaFuncAttributeMaxDynamicSharedMemorySize, SMEM_TOTAL);

    prep_w_kernel<<<(NTAP*CO*CI + 255)/256, 256>>>(sw);
    conv_mma_kernel<<<dim3(52, BATCH), 512, SMEM_TOTAL>>>(x, offset, out);
}

// round 9
// speedup vs baseline: 10.7505x; 1.0258x over previous
#include <cuda_runtime.h>
#include <cuda_fp16.h>
#include <cstdint>
#include <math.h>

#define BATCH 16
#define H 209
#define W 133
#define CI 64
#define CO 128
#define NTAP 19
#define OHH 201
#define OWW 129

// hex_indices(2) order (t matches sparse_weights layout) — validated in R1
__constant__ int c_dh[NTAP] = {4,3,5,6,5,3,2,1,2,4,6,7,8,7,6,4,2,1,0};
__constant__ int c_dw[NTAP] = {2,3,3,2,1,1,2,3,4,4,4,3,2,1,0,0,0,1,2};

// prepped weights: [t][co][ci] fp16
__device__ __align__(16) __half g_w[NTAP*CO*CI];

__device__ __forceinline__ uint32_t smem_u32(const void* p) {
    uint32_t a;
    asm("{ .reg .u64 t; cvta.to.shared.u64 t, %1; cvt.u32.u64 %0, t; }" : "=r"(a) : "l"(p));
    return a;
}
__device__ __forceinline__ uint32_t pack2h(__half a, __half b) {
    return (uint32_t)__half_as_ushort(a) | ((uint32_t)__half_as_ushort(b) << 16);
}
__device__ __forceinline__ uint2 cvt4(float4 v) {
    return make_uint2(pack2h(__float2half_rn(v.x), __float2half_rn(v.y)),
                      pack2h(__float2half_rn(v.z), __float2half_rn(v.w)));
}

#define LDSM4(r, addr)                                                          \
    asm volatile("ldmatrix.sync.aligned.m8n8.x4.shared.b16 {%0,%1,%2,%3}, [%4];"\
        : "=r"((r)[0]), "=r"((r)[1]), "=r"((r)[2]), "=r"((r)[3]) : "r"(addr))

#define MMA16816(c, a, b0, b1)                                                  \
    asm volatile("mma.sync.aligned.m16n8k16.row.col.f32.f16.f16.f32 "           \
        "{%0,%1,%2,%3}, {%4,%5,%6,%7}, {%8,%9}, {%0,%1,%2,%3};"                 \
        : "+f"((c)[0]), "+f"((c)[1]), "+f"((c)[2]), "+f"((c)[3])                \
        : "r"((a)[0]), "r"((a)[1]), "r"((a)[2]), "r"((a)[3]), "r"(b0), "r"(b1))

#define CP_ASYNC(dst, src, sz)                                                  \
    asm volatile("cp.async.cg.shared.global [%0], [%1], 16, %2;"                \
        :: "r"(dst), "l"(src), "r"(sz))
#define CP_COMMIT() asm volatile("cp.async.commit_group;" ::: "memory")
#define CP_WAIT(n)  asm volatile("cp.async.wait_group %0;" :: "n"(n) : "memory")

// ---------------- prep: weights to fp16, layout [t][co][ci] ----------------
__global__ void prep_w_kernel(const float* __restrict__ sw) {
    int i = blockIdx.x * blockDim.x + threadIdx.x;
    if (i >= NTAP*CO*CI) return;
    int ci = i & 63;
    int co = (i >> 6) & 127;
    int t  = i >> 13;
    g_w[i] = __float2half_rn(sw[(ci*CO + co)*NTAP + t]);
}

// ---------------- main mma.sync kernel ----------------
// grid (52, 16), 512 threads (16 warps: 4 M x 4 N).
// conv CTAs: fp16 x-slab (12 rows x 68 wc x 128B) built once; B in 6-slot 16KB ring;
//            ONE barrier per TWO taps; fragment-pipelined compute.
// edge CTA (blockIdx.x==51): per-tap loop, A 3-slot ring in slab area.
#define SLAB_WC     68
#define SLAB_SLOTS  (12*SLAB_WC)        // 816
#define SLAB_BYTES  (SLAB_SLOTS*128)    // 104448
#define BOFF        SLAB_BYTES
#define NBRING      6
#define SMEM_TOTAL  (SLAB_BYTES + NBRING*16384 + 512)   // 203264

__global__ __launch_bounds__(512, 1)
void conv_mma_kernel(const float* __restrict__ x,
                     const float* __restrict__ off, float* __restrict__ out) {
    extern __shared__ __align__(1024) char smem[];
    const uint32_t smem_base = smem_u32(smem);
    const int tid    = threadIdx.x;
    const int lane   = tid & 31;
    const int wid    = tid >> 5;
    const int warp_m = wid >> 2;       // 0..3
    const int warp_n = wid & 3;        // 0..3
    const int b      = blockIdx.y;
    const bool is_edge = (blockIdx.x == 51);
    const int r0     = blockIdx.x * 4; // first output row (conv path)

    float* s_off = (float*)(smem + SMEM_TOTAL - 512);
    if (tid < CO) s_off[tid] = off[tid];

    if (is_edge) {
        for (int e = tid; e < OHH*CO; e += 512) {
            int oh = e >> 7, co = e & 127;
            out[((size_t)(b*OHH + oh)*OWW + 128)*CO + co] = 0.f;
        }
    }

    const float* xb = x + (size_t)b * H * W * CI;

    // per-lane pieces of A/B ldmatrix addressing
    const uint32_t laneoA = (uint32_t)((lane & 15)*128 + ((lane >> 4) & 1)*16);
    const int rowB   = warp_n*32 + (lane & 7) + ((lane >> 4) & 1)*8;
    const uint32_t baseB = (uint32_t)(rowB*128 + ((lane >> 3) & 1)*16);
    const uint32_t mB = (uint32_t)(rowB & 7) << 4;

    float c[4][4][4];
    #pragma unroll
    for (int i = 0; i < 4; ++i)
        #pragma unroll
        for (int j = 0; j < 4; ++j)
            #pragma unroll
            for (int k = 0; k < 4; ++k) c[i][j][k] = 0.f;

    // ---- B stage for tap t into ring slot t%6 (cp.async, one group) ----
    auto issue_B = [&](int t) {
        uint32_t bufa = smem_base + BOFF + (uint32_t)((t % NBRING)*16384);
        #pragma unroll
        for (int i = 0; i < 2; ++i) {
            int e  = tid + i*512;
            int c8 = e & 7;
            int co = e >> 3;
            uint32_t o = (uint32_t)(co*128 + c8*16);
            o ^= (o >> 3) & 0x70;
            CP_ASYNC(bufa + o, g_w + (size_t)t*CO*CI + co*CI + c8*8, 16);
        }
        CP_COMMIT();
    };

    // ---- edge A tile for tap t: f32 LDG -> fp16 STS into 3-slot ring ----
    auto stage_A_edge = [&](int t) {
        char* bufp = smem + (t % 3)*32768;
        const int dh = c_dh[t], dw = c_dw[t];
        #pragma unroll
        for (int i = 0; i < 8; ++i) {
            int e  = tid + i*512;          // 0..4095: 256 m x 16 c4
            int c4 = e & 15;
            int m  = e >> 4;
            float4 v = make_float4(0.f,0.f,0.f,0.f);
            if (m <= 100)
                v = *(const float4*)(xb + ((size_t)(2*m + dh)*W + 128 + dw)*CI + c4*4);
            uint32_t o = (uint32_t)(m*128 + c4*8);
            o ^= (o >> 3) & 0x70;
            *(uint2*)(bufp + o) = cvt4(v);
        }
    };

    // ---- fragment-pipelined compute of one tap ----
    auto compute = [&](uint32_t bufA, int rbase, uint32_t bufB) {
        const uint32_t maskA  = (uint32_t)(((rbase + (lane & 15)) & 7) << 4);
        const uint32_t baseoA = (uint32_t)(rbase*128) + laneoA;
        uint32_t bfr[2][2][4];
        #pragma unroll
        for (int q = 0; q < 2; ++q)
            LDSM4(bfr[0][q], bufB + ((baseB + (uint32_t)(q*2048)) ^ mB));
        #pragma unroll
        for (int ks = 0; ks < 4; ++ks) {
            const int cur = ks & 1, nxt = cur ^ 1;
            if (ks < 3) {
                #pragma unroll
                for (int q = 0; q < 2; ++q)
                    LDSM4(bfr[nxt][q], bufB + ((baseB + (uint32_t)(q*2048 + (ks+1)*32)) ^ mB));
            }
            uint32_t afr[2][4];
            LDSM4(afr[0], bufA + ((baseoA + (uint32_t)(ks*32)) ^ maskA));
            #pragma unroll
            for (int mt = 0; mt < 4; ++mt) {
                if (mt < 3)
                    LDSM4(afr[(mt+1)&1],
                          bufA + ((baseoA + (uint32_t)((mt+1)*2048 + ks*32)) ^ maskA));
                #pragma unroll
                for (int nt = 0; nt < 4; ++nt) {
                    int q = nt >> 1, h = (nt & 1)*2;
                    MMA16816(c[mt][nt], afr[mt&1], bfr[cur][q][h], bfr[cur][q][h+1]);
                }
            }
        }
    };

    if (!is_edge) {
        // ---- B ring prefill (4 groups) ----
        issue_B(0); issue_B(1); issue_B(2); issue_B(3);

        // ---- build fp16 slab from f32 x (once) ----
        for (int e = tid; e < SLAB_SLOTS*16; e += 512) {
            int c4   = e & 15;
            int slot = e >> 4;               // 0..815
            int hr   = slot / SLAB_WC;
            int wc   = slot - hr*SLAB_WC;
            int hrow = r0 + hr;
            int w    = 2*wc + (hrow & 1);
            float4 v = make_float4(0.f,0.f,0.f,0.f);
            if (hrow <= 208 && w <= 132)
                v = *(const float4*)(xb + ((size_t)hrow*W + w)*CI + c4*4);
            uint32_t o = (uint32_t)(slot*128 + c4*8);
            o ^= (o >> 3) & 0x70;
            *(uint2*)(smem + o) = cvt4(v);
        }

        const int rp = (r0 + warp_m) & 1;
        auto do_tap = [&](int t) {
            const int dh = c_dh[t], dw = c_dw[t];
            const int hp = (rp + dh) & 1;
            const int wc0 = (rp + dw - hp) >> 1;
            compute(smem_base, (warp_m + dh)*SLAB_WC + wc0,
                    smem_base + BOFF + (uint32_t)((t % NBRING)*16384));
        };

        // ---- 2 taps per barrier (pairs 0..17), tail tap 18 ----
        for (int s = 0; s + 1 < NTAP; s += 2) {
            CP_WAIT(2);
            __syncthreads();
            do_tap(s);
            do_tap(s + 1);
            if (s + 4 < NTAP) issue_B(s + 4);
            if (s + 5 < NTAP) issue_B(s + 5);
        }
        CP_WAIT(0);
        __syncthreads();
        do_tap(NTAP - 1);

        // ---- conv epilogue ----
        const int co0 = warp_n*32 + (lane & 3)*2;
        const int row = r0 + warp_m;
        if (row <= 200) {
            const int p   = row & 1;
            const int adi = row > 100 ? row - 100 : 100 - row;
            float* rbaseo = out + ((size_t)(b*OHH + row) * OWW) * CO;
            const float2 z2 = make_float2(0.f, 0.f);
            #pragma unroll
            for (int mt = 0; mt < 4; ++mt) {
                #pragma unroll
                for (int hf = 0; hf < 2; ++hf) {
                    int owc = mt*16 + (lane >> 2) + hf*8;
                    int ow  = 2*owc + p;
                    int owz = p ? (ow - 1) : (ow + 1);
                    int adj = ow > 64 ? ow - 64 : 64 - ow;
                    bool valid = (adi + adj) <= 128;
                    float* vb = rbaseo + (size_t)ow  * CO;
                    float* zb = rbaseo + (size_t)owz * CO;
                    #pragma unroll
                    for (int nt = 0; nt < 4; ++nt) {
                        int co = co0 + nt*8;
                        float v0 = c[mt][nt][hf*2+0] + s_off[co];
                        float v1 = c[mt][nt][hf*2+1] + s_off[co+1];
                        v0 = v0 > 0.f ? v0 : expm1f(v0);
                        v1 = v1 > 0.f ? v1 : expm1f(v1);
                        *(float2*)(vb + co) = valid ? make_float2(v0, v1) : z2;
                        *(float2*)(zb + co) = z2;
                    }
                }
            }
        }
    } else {
        issue_B(0); issue_B(1);
        stage_A_edge(0); stage_A_edge(1);
        for (int t = 0; t < NTAP; ++t) {
            if (t + 2 < NTAP) { CP_WAIT(1); } else { CP_WAIT(0); }
            __syncthreads();
            compute(smem_base + (uint32_t)((t % 3)*32768), warp_m*64,
                    smem_base + BOFF + (uint32_t)((t % NBRING)*16384));
            if (t + 2 < NTAP) { issue_B(t + 2); stage_A_edge(t + 2); }
        }

        // ---- edge epilogue: row m -> oh=2m, ow=128; valid iff oh in [36,164] ----
        const int co0 = warp_n*32 + (lane & 3)*2;
        #pragma unroll
        for (int mt = 0; mt < 4; ++mt) {
            #pragma unroll
            for (int hf = 0; hf < 2; ++hf) {
                int m  = warp_m*64 + mt*16 + (lane >> 2) + hf*8;
                int oh = 2*m;
                if (m <= 100 && oh >= 36 && oh <= 164) {
                    float* vb = out + ((size_t)(b*OHH + oh)*OWW + 128)*CO;
                    #pragma unroll
                    for (int nt = 0; nt < 4; ++nt) {
                        int co = co0 + nt*8;
                        float v0 = c[mt][nt][hf*2+0] + s_off[co];
                        float v1 = c[mt][nt][hf*2+1] + s_off[co+1];
                        v0 = v0 > 0.f ? v0 : expm1f(v0);
                        v1 = v1 > 0.f ? v1 : expm1f(v1);
                        *(float2*)(vb + co) = make_float2(v0, v1);
                    }
                }
            }
        }
    }
}

extern "C" void kernel_launch(void* const* d_in, const int* in_sizes, int n_in,
                              void* d_out, int out_size) {
    const float* x      = (const float*)d_in[0];   // [16,209,133,64]
    const float* sw     = (const float*)d_in[1];   // [19*64*128] as [ci][co][t]
    const float* offset = (const float*)d_in[2];   // [128]
    float* out = (float*)d_out;

    cudaFuncSetAttribute(conv_mma_kernel,
                         cudaFuncAttributeMaxDynamicSharedMemorySize, SMEM_TOTAL);

    prep_w_kernel<<<(NTAP*CO*CI + 255)/256, 256>>>(sw);
    conv_mma_kernel<<<dim3(52, BATCH), 512, SMEM_TOTAL>>>(x, offset, out);
}

// round 10
// speedup vs baseline: 10.8429x; 1.0086x over previous
#include <cuda_runtime.h>
#include <cuda_fp16.h>
#include <cstdint>
#include <math.h>

#define BATCH 16
#define H 209
#define W 133
#define CI 64
#define CO 128
#define NTAP 19
#define OHH 201
#define OWW 129

// hex_indices(2) order (t matches sparse_weights layout) — validated in R1
__constant__ int c_dh[NTAP] = {4,3,5,6,5,3,2,1,2,4,6,7,8,7,6,4,2,1,0};
__constant__ int c_dw[NTAP] = {2,3,3,2,1,1,2,3,4,4,4,3,2,1,0,0,0,1,2};

// prepped weights: [t][co][ci] fp16
__device__ __align__(16) __half g_w[NTAP*CO*CI];

__device__ __forceinline__ uint32_t smem_u32(const void* p) {
    uint32_t a;
    asm("{ .reg .u64 t; cvta.to.shared.u64 t, %1; cvt.u32.u64 %0, t; }" : "=r"(a) : "l"(p));
    return a;
}
__device__ __forceinline__ uint32_t pack2h(__half a, __half b) {
    return (uint32_t)__half_as_ushort(a) | ((uint32_t)__half_as_ushort(b) << 16);
}
__device__ __forceinline__ uint2 cvt4(float4 v) {
    return make_uint2(pack2h(__float2half_rn(v.x), __float2half_rn(v.y)),
                      pack2h(__float2half_rn(v.z), __float2half_rn(v.w)));
}

#define LDSM4(r, addr)                                                          \
    asm volatile("ldmatrix.sync.aligned.m8n8.x4.shared.b16 {%0,%1,%2,%3}, [%4];"\
        : "=r"((r)[0]), "=r"((r)[1]), "=r"((r)[2]), "=r"((r)[3]) : "r"(addr))

#define MMA16816(c, a, b0, b1)                                                  \
    asm volatile("mma.sync.aligned.m16n8k16.row.col.f32.f16.f16.f32 "           \
        "{%0,%1,%2,%3}, {%4,%5,%6,%7}, {%8,%9}, {%0,%1,%2,%3};"                 \
        : "+f"((c)[0]), "+f"((c)[1]), "+f"((c)[2]), "+f"((c)[3])                \
        : "r"((a)[0]), "r"((a)[1]), "r"((a)[2]), "r"((a)[3]), "r"(b0), "r"(b1))

#define CP_ASYNC(dst, src, sz)                                                  \
    asm volatile("cp.async.cg.shared.global [%0], [%1], 16, %2;"                \
        :: "r"(dst), "l"(src), "r"(sz))
#define CP_COMMIT() asm volatile("cp.async.commit_group;" ::: "memory")
#define CP_WAIT(n)  asm volatile("cp.async.wait_group %0;" :: "n"(n) : "memory")

// ---------------- prep: weights to fp16, layout [t][co][ci] ----------------
__global__ void prep_w_kernel(const float* __restrict__ sw) {
    int i = blockIdx.x * blockDim.x + threadIdx.x;
    if (i >= NTAP*CO*CI) return;
    int ci = i & 63;
    int co = (i >> 6) & 127;
    int t  = i >> 13;
    g_w[i] = __float2half_rn(sw[(ci*CO + co)*NTAP + t]);
}

// ---------------- main mma.sync kernel ----------------
// grid (52, 16), 512 threads (16 warps: 4 M x 4 N).
// PITCH-144 layout (no XOR swizzle): rows at 144B stride -> ldmatrix 8x8 tiles
// hit banks 4r mod 32 (conflict-free) with purely ADDITIVE addressing.
// conv CTAs: fp16 x-slab (12 rows x 68 wc, pitch 144) built once;
//            B in 6-slot (128 rows x 144B = 18432B) ring; barrier per 2 taps.
// edge CTA (blockIdx.x==51): per-tap A tile (256 rows x 144B, 3-slot ring).
#define PITCH       144
#define SLAB_WC     68
#define SLAB_SLOTS  (12*SLAB_WC)            // 816
#define SLAB_BYTES  (SLAB_SLOTS*PITCH)      // 117504
#define BOFF        SLAB_BYTES
#define BSLOT       (CO*PITCH)              // 18432
#define NBRING      6
#define SMEM_TOTAL  (SLAB_BYTES + NBRING*BSLOT + 512)   // 228608

__global__ __launch_bounds__(512, 1)
void conv_mma_kernel(const float* __restrict__ x,
                     const float* __restrict__ off, float* __restrict__ out) {
    extern __shared__ __align__(1024) char smem[];
    const uint32_t smem_base = smem_u32(smem);
    const int tid    = threadIdx.x;
    const int lane   = tid & 31;
    const int wid    = tid >> 5;
    const int warp_m = wid >> 2;       // 0..3
    const int warp_n = wid & 3;        // 0..3
    const int b      = blockIdx.y;
    const bool is_edge = (blockIdx.x == 51);
    const int r0     = blockIdx.x * 4; // first output row (conv path)

    float* s_off = (float*)(smem + SMEM_TOTAL - 512);
    if (tid < CO) s_off[tid] = off[tid];

    if (is_edge) {
        for (int e = tid; e < OHH*CO; e += 512) {
            int oh = e >> 7, co = e & 127;
            out[((size_t)(b*OHH + oh)*OWW + 128)*CO + co] = 0.f;
        }
    }

    const float* xb = x + (size_t)b * H * W * CI;

    // per-lane ldmatrix offsets (additive; no swizzle)
    const uint32_t laneoA = (uint32_t)((lane & 15)*PITCH + ((lane >> 4) & 1)*16);
    const uint32_t laneoB = (uint32_t)((warp_n*32 + (lane & 7) + ((lane >> 4) & 1)*8)*PITCH
                                        + ((lane >> 3) & 1)*16);

    float c[4][4][4];
    #pragma unroll
    for (int i = 0; i < 4; ++i)
        #pragma unroll
        for (int j = 0; j < 4; ++j)
            #pragma unroll
            for (int k = 0; k < 4; ++k) c[i][j][k] = 0.f;

    // ---- B stage for tap t into ring slot t%6 (cp.async, one group) ----
    auto issue_B = [&](int t) {
        uint32_t bufa = smem_base + BOFF + (uint32_t)((t % NBRING)*BSLOT);
        #pragma unroll
        for (int i = 0; i < 2; ++i) {
            int e  = tid + i*512;
            int c8 = e & 7;
            int co = e >> 3;
            CP_ASYNC(bufa + (uint32_t)(co*PITCH + c8*16),
                     g_w + (size_t)t*CO*CI + co*CI + c8*8, 16);
        }
        CP_COMMIT();
    };

    // ---- edge A tile for tap t: f32 LDG -> fp16 STS into 3-slot ring ----
    auto stage_A_edge = [&](int t) {
        char* bufp = smem + (t % 3)*(256*PITCH);
        const int dh = c_dh[t], dw = c_dw[t];
        #pragma unroll
        for (int i = 0; i < 8; ++i) {
            int e  = tid + i*512;          // 0..4095: 256 m x 16 c4
            int c4 = e & 15;
            int m  = e >> 4;
            float4 v = make_float4(0.f,0.f,0.f,0.f);
            if (m <= 100)
                v = *(const float4*)(xb + ((size_t)(2*m + dh)*W + 128 + dw)*CI + c4*4);
            *(uint2*)(bufp + m*PITCH + c4*8) = cvt4(v);
        }
    };

    // ---- compute one tap: A tile base address abase (additive), B in bufB ----
    auto compute = [&](uint32_t abase, uint32_t bufB) {
        const uint32_t a0 = abase + laneoA;
        const uint32_t b0 = bufB + laneoB;
        #pragma unroll
        for (int ks = 0; ks < 4; ++ks) {
            uint32_t bh[2][4];
            #pragma unroll
            for (int q = 0; q < 2; ++q)
                LDSM4(bh[q], b0 + (uint32_t)(q*16*PITCH + ks*32));
            #pragma unroll
            for (int mt = 0; mt < 4; ++mt) {
                uint32_t ah[4];
                LDSM4(ah, a0 + (uint32_t)(mt*16*PITCH + ks*32));
                #pragma unroll
                for (int nt = 0; nt < 4; ++nt) {
                    int q = nt >> 1, h = (nt & 1)*2;
                    MMA16816(c[mt][nt], ah, bh[q][h], bh[q][h+1]);
                }
            }
        }
    };

    if (!is_edge) {
        // ---- B ring prefill (4 groups) ----
        issue_B(0); issue_B(1); issue_B(2); issue_B(3);

        // ---- build fp16 slab from f32 x (once) ----
        for (int e = tid; e < SLAB_SLOTS*16; e += 512) {
            int c4   = e & 15;
            int slot = e >> 4;               // 0..815
            int hr   = slot / SLAB_WC;
            int wc   = slot - hr*SLAB_WC;
            int hrow = r0 + hr;
            int w    = 2*wc + (hrow & 1);
            float4 v = make_float4(0.f,0.f,0.f,0.f);
            if (hrow <= 208 && w <= 132)
                v = *(const float4*)(xb + ((size_t)hrow*W + w)*CI + c4*4);
            *(uint2*)(smem + slot*PITCH + c4*8) = cvt4(v);
        }

        const int rp = (r0 + warp_m) & 1;
        auto do_tap = [&](int t) {
            const int dh = c_dh[t], dw = c_dw[t];
            const int hp = (rp + dh) & 1;
            const int wc0 = (rp + dw - hp) >> 1;
            compute(smem_base + (uint32_t)(((warp_m + dh)*SLAB_WC + wc0)*PITCH),
                    smem_base + BOFF + (uint32_t)((t % NBRING)*BSLOT));
        };

        // ---- 2 taps per barrier (pairs 0..17), tail tap 18 ----
        for (int s = 0; s + 1 < NTAP; s += 2) {
            CP_WAIT(2);
            __syncthreads();
            do_tap(s);
            do_tap(s + 1);
            if (s + 4 < NTAP) issue_B(s + 4);
            if (s + 5 < NTAP) issue_B(s + 5);
        }
        CP_WAIT(0);
        __syncthreads();
        do_tap(NTAP - 1);

        // ---- conv epilogue ----
        const int co0 = warp_n*32 + (lane & 3)*2;
        const int row = r0 + warp_m;
        if (row <= 200) {
            const int p   = row & 1;
            const int adi = row > 100 ? row - 100 : 100 - row;
            float* rbaseo = out + ((size_t)(b*OHH + row) * OWW) * CO;
            const float2 z2 = make_float2(0.f, 0.f);
            #pragma unroll
            for (int mt = 0; mt < 4; ++mt) {
                #pragma unroll
                for (int hf = 0; hf < 2; ++hf) {
                    int owc = mt*16 + (lane >> 2) + hf*8;
                    int ow  = 2*owc + p;
                    int owz = p ? (ow - 1) : (ow + 1);
                    int adj = ow > 64 ? ow - 64 : 64 - ow;
                    bool valid = (adi + adj) <= 128;
                    float* vb = rbaseo + (size_t)ow  * CO;
                    float* zb = rbaseo + (size_t)owz * CO;
                    #pragma unroll
                    for (int nt = 0; nt < 4; ++nt) {
                        int co = co0 + nt*8;
                        float v0 = c[mt][nt][hf*2+0] + s_off[co];
                        float v1 = c[mt][nt][hf*2+1] + s_off[co+1];
                        v0 = v0 > 0.f ? v0 : (__expf(v0) - 1.0f);
                        v1 = v1 > 0.f ? v1 : (__expf(v1) - 1.0f);
                        *(float2*)(vb + co) = valid ? make_float2(v0, v1) : z2;
                        *(float2*)(zb + co) = z2;
                    }
                }
            }
        }
    } else {
        issue_B(0); issue_B(1);
        stage_A_edge(0); stage_A_edge(1);
        for (int t = 0; t < NTAP; ++t) {
            if (t + 2 < NTAP) { CP_WAIT(1); } else { CP_WAIT(0); }
            __syncthreads();
            compute(smem_base + (uint32_t)((t % 3)*(256*PITCH) + warp_m*64*PITCH),
                    smem_base + BOFF + (uint32_t)((t % NBRING)*BSLOT));
            if (t + 2 < NTAP) { issue_B(t + 2); stage_A_edge(t + 2); }
        }

        // ---- edge epilogue: row m -> oh=2m, ow=128; valid iff oh in [36,164] ----
        const int co0 = warp_n*32 + (lane & 3)*2;
        #pragma unroll
        for (int mt = 0; mt < 4; ++mt) {
            #pragma unroll
            for (int hf = 0; hf < 2; ++hf) {
                int m  = warp_m*64 + mt*16 + (lane >> 2) + hf*8;
                int oh = 2*m;
                if (m <= 100 && oh >= 36 && oh <= 164) {
                    float* vb = out + ((size_t)(b*OHH + oh)*OWW + 128)*CO;
                    #pragma unroll
                    for (int nt = 0; nt < 4; ++nt) {
                        int co = co0 + nt*8;
                        float v0 = c[mt][nt][hf*2+0] + s_off[co];
                        float v1 = c[mt][nt][hf*2+1] + s_off[co+1];
                        v0 = v0 > 0.f ? v0 : (__expf(v0) - 1.0f);
                        v1 = v1 > 0.f ? v1 : (__expf(v1) - 1.0f);
                        *(float2*)(vb + co) = make_float2(v0, v1);
                    }
                }
            }
        }
    }
}

extern "C" void kernel_launch(void* const* d_in, const int* in_sizes, int n_in,
                              void* d_out, int out_size) {
    const float* x      = (const float*)d_in[0];   // [16,209,133,64]
    const float* sw     = (const float*)d_in[1];   // [19*64*128] as [ci][co][t]
    const float* offset = (const float*)d_in[2];   // [128]
    float* out = (float*)d_out;

    cudaFuncSetAttribute(conv_mma_kernel,
                         cudaFuncAttributeMaxDynamicSharedMemorySize, SMEM_TOTAL);

    prep_w_kernel<<<(NTAP*CO*CI + 255)/256, 256>>>(sw);
    conv_mma_kernel<<<dim3(52, BATCH), 512, SMEM_TOTAL>>>(x, offset, out);
}